// round 3
// baseline (speedup 1.0000x reference)
#include <cuda_runtime.h>
#include <math.h>

// ---------------------------------------------------------------------------
// Problem constants
//   B=2, S_X=S_Y=2048, C1=C2=1024, H=16, D=64, W_EXP=4
//   rows_x = B*S_X = 4096, rows_y = 4096, H*D = 1024
// ---------------------------------------------------------------------------

// ---------------- scratch (static __device__ — allocation-free) ------------
__device__ float g_xn  [4096 * 1024];
__device__ float g_yn  [4096 * 1024];
__device__ float g_wqp [1024 * 1024];
__device__ float g_wkp [1024 * 1024];
__device__ float g_wvp [1024 * 1024];
__device__ float g_q   [4096 * 1024];
__device__ float g_k   [4096 * 1024];
__device__ float g_v   [4096 * 1024];
__device__ float g_p   [134217728];      // [32][2048][2048] scores -> probs (512 MB)
__device__ float g_o   [4096 * 1024];
__device__ float g_xout[4096 * 1024];
__device__ float g_h1  [4096 * 1024];
__device__ float g_h2  [4096 * 4096];

// ---------------------------------------------------------------------------
// LayerNorm over last dim (C = 1024). One block per row, 256 thr x 4 elems.
// ---------------------------------------------------------------------------
__global__ void ln_kernel(const float* __restrict__ x,
                          const float* __restrict__ w,
                          const float* __restrict__ b,
                          float* __restrict__ out)
{
    __shared__ float shs[8], shq[8];
    const int row = blockIdx.x;
    const float* xr = x + (long long)row * 1024;
    float*       orow = out + (long long)row * 1024;
    const int t = threadIdx.x;

    float4 f = *(const float4*)(xr + t * 4);
    float s = f.x + f.y + f.z + f.w;
    float q = f.x * f.x + f.y * f.y + f.z * f.z + f.w * f.w;
    #pragma unroll
    for (int o = 16; o; o >>= 1) {
        s += __shfl_xor_sync(0xFFFFFFFFu, s, o);
        q += __shfl_xor_sync(0xFFFFFFFFu, q, o);
    }
    const int wid = t >> 5, ln = t & 31;
    if (ln == 0) { shs[wid] = s; shq[wid] = q; }
    __syncthreads();
    if (wid == 0) {
        float a = (ln < 8) ? shs[ln] : 0.0f;
        float c = (ln < 8) ? shq[ln] : 0.0f;
        #pragma unroll
        for (int o = 4; o; o >>= 1) {
            a += __shfl_xor_sync(0xFFFFFFFFu, a, o);
            c += __shfl_xor_sync(0xFFFFFFFFu, c, o);
        }
        if (ln == 0) { shs[0] = a; shq[0] = c; }
    }
    __syncthreads();
    const float mu  = shs[0] * (1.0f / 1024.0f);
    const float var = shq[0] * (1.0f / 1024.0f) - mu * mu;
    const float rs  = rsqrtf(var + 1e-5f);

    float4 wv = *(const float4*)(w + t * 4);
    float4 bv = *(const float4*)(b + t * 4);
    float4 ov;
    ov.x = (f.x - mu) * rs * wv.x + bv.x;
    ov.y = (f.y - mu) * rs * wv.y + bv.y;
    ov.z = (f.z - mu) * rs * wv.z + bv.z;
    ov.w = (f.w - mu) * rs * wv.w + bv.w;
    *(float4*)(orow + t * 4) = ov;
}

// ---------------------------------------------------------------------------
// Pack per-head weights [H, C, D] -> [C, H*D] so all projections are NN GEMMs.
// ---------------------------------------------------------------------------
__global__ void pack_w_kernel(const float* __restrict__ Wq,
                              const float* __restrict__ Wk,
                              const float* __restrict__ Wv)
{
    const int i = blockIdx.x * 256 + threadIdx.x;   // 0 .. 1M-1
    const int c = i >> 10;
    const int j = i & 1023;
    const int h = j >> 6;
    const int d = j & 63;
    const int src = h * 65536 + c * 64 + d;         // h*C*D + c*D + d
    g_wqp[i] = Wq[src];
    g_wkp[i] = Wk[src];
    g_wvp[i] = Wv[src];
}

// ---------------------------------------------------------------------------
// Full-row softmax over 2048 cols, then zero entries with t <= s (mask AFTER
// softmax, so the denominator uses all t). In-place on g_p.
// grid = 65536 rows (z*2048 + s), block = 256 (8 elems/thread).
// ---------------------------------------------------------------------------
__global__ void softmax_mask_kernel()
{
    __shared__ float sh[8];
    const long long row = blockIdx.x;
    const int s = (int)(row & 2047);
    float* p = g_p + row * 2048;
    const int t = threadIdx.x;
    const int t0 = t * 8;

    float4 f1 = *(const float4*)(p + t0);
    float4 f2 = *(const float4*)(p + t0 + 4);
    float v[8] = {f1.x, f1.y, f1.z, f1.w, f2.x, f2.y, f2.z, f2.w};

    float mx = v[0];
    #pragma unroll
    for (int j = 1; j < 8; ++j) mx = fmaxf(mx, v[j]);
    #pragma unroll
    for (int o = 16; o; o >>= 1) mx = fmaxf(mx, __shfl_xor_sync(0xFFFFFFFFu, mx, o));
    const int wid = t >> 5, ln = t & 31;
    if (ln == 0) sh[wid] = mx;
    __syncthreads();
    if (wid == 0) {
        float a = (ln < 8) ? sh[ln] : -3.0e38f;
        #pragma unroll
        for (int o = 4; o; o >>= 1) a = fmaxf(a, __shfl_xor_sync(0xFFFFFFFFu, a, o));
        if (ln == 0) sh[0] = a;
    }
    __syncthreads();
    const float M = sh[0];
    __syncthreads();

    float e[8];
    float sum = 0.0f;
    #pragma unroll
    for (int j = 0; j < 8; ++j) { e[j] = __expf(v[j] - M); sum += e[j]; }
    #pragma unroll
    for (int o = 16; o; o >>= 1) sum += __shfl_xor_sync(0xFFFFFFFFu, sum, o);
    if (ln == 0) sh[wid] = sum;
    __syncthreads();
    if (wid == 0) {
        float a = (ln < 8) ? sh[ln] : 0.0f;
        #pragma unroll
        for (int o = 4; o; o >>= 1) a += __shfl_xor_sync(0xFFFFFFFFu, a, o);
        if (ln == 0) sh[0] = a;
    }
    __syncthreads();
    const float inv = 1.0f / sh[0];

    float r[8];
    #pragma unroll
    for (int j = 0; j < 8; ++j) r[j] = (t0 + j > s) ? e[j] * inv : 0.0f;
    float4 o1, o2;
    o1.x = r[0]; o1.y = r[1]; o1.z = r[2]; o1.w = r[3];
    o2.x = r[4]; o2.y = r[5]; o2.z = r[6]; o2.w = r[7];
    *(float4*)(p + t0)     = o1;
    *(float4*)(p + t0 + 4) = o2;
}

// ---------------------------------------------------------------------------
// Generic fp32 GEMM: C = epi(A @ B(^T))  with 128x64 tile, BK=16, 256 threads,
// 8x4 register micro-tile. All problem dims divide the tiles exactly.
// Batch z: operand offset = (z>>4)*SB + (z&15)*SH  (H=16 head decomposition).
// EPI: 0 = alpha*acc ; 1 = acc + bias[n] + res[m][n] ; 2 = gelu(acc + bias[n])
// ---------------------------------------------------------------------------
template<int EPI, bool TRANSB>
__global__ __launch_bounds__(256)
void gemm_kernel(int M, int N, int K,
                 const float* __restrict__ A, int lda, long long aSB, long long aSH,
                 const float* __restrict__ B, int ldb, long long bSB, long long bSH,
                 float* __restrict__ C, int ldc, long long cSB, long long cSH,
                 float alpha,
                 const float* __restrict__ bias,
                 const float* __restrict__ res, int ldr)
{
    __shared__ float As[16][128];
    __shared__ float Bs[16][64];

    const int z  = blockIdx.z;
    const long long zb = z >> 4, zh = z & 15;
    A += zb * aSB + zh * aSH;
    B += zb * bSB + zh * bSH;
    C += zb * cSB + zh * cSH;

    const int bm = blockIdx.y * 128;
    const int bn = blockIdx.x * 64;
    const int t  = threadIdx.x;
    const int tx = t & 15;
    const int ty = t >> 4;

    float acc[8][4];
    #pragma unroll
    for (int i = 0; i < 8; ++i)
        #pragma unroll
        for (int j = 0; j < 4; ++j) acc[i][j] = 0.0f;

    const int nk = K >> 4;
    for (int kt = 0; kt < nk; ++kt) {
        // --- load A tile [128 x 16] transposed into As[k][m] ---
        #pragma unroll
        for (int r = 0; r < 2; ++r) {
            const int id = t + r * 256;          // 0..511
            const int m  = id >> 2;              // 0..127
            const int k4 = (id & 3) << 2;        // 0,4,8,12
            float4 f = *(const float4*)(A + (long long)(bm + m) * lda + (kt << 4) + k4);
            As[k4 + 0][m] = f.x;
            As[k4 + 1][m] = f.y;
            As[k4 + 2][m] = f.z;
            As[k4 + 3][m] = f.w;
        }
        // --- load B tile [16 x 64] into Bs[k][n] ---
        if (!TRANSB) {
            const int k  = t >> 4;               // 0..15
            const int n4 = (t & 15) << 2;        // 0..60
            *(float4*)&Bs[k][n4] =
                *(const float4*)(B + (long long)((kt << 4) + k) * ldb + bn + n4);
        } else {
            const int n  = t >> 2;               // 0..63
            const int k4 = (t & 3) << 2;         // 0,4,8,12
            float4 f = *(const float4*)(B + (long long)(bn + n) * ldb + (kt << 4) + k4);
            Bs[k4 + 0][n] = f.x;
            Bs[k4 + 1][n] = f.y;
            Bs[k4 + 2][n] = f.z;
            Bs[k4 + 3][n] = f.w;
        }
        __syncthreads();

        #pragma unroll
        for (int kk = 0; kk < 16; ++kk) {
            float4 a0 = *(float4*)&As[kk][ty * 8];
            float4 a1 = *(float4*)&As[kk][ty * 8 + 4];
            float4 b0 = *(float4*)&Bs[kk][tx * 4];
            float ar[8] = {a0.x, a0.y, a0.z, a0.w, a1.x, a1.y, a1.z, a1.w};
            float br[4] = {b0.x, b0.y, b0.z, b0.w};
            #pragma unroll
            for (int i = 0; i < 8; ++i)
                #pragma unroll
                for (int j = 0; j < 4; ++j)
                    acc[i][j] = fmaf(ar[i], br[j], acc[i][j]);
        }
        __syncthreads();
    }

    // --- epilogue ---
    #pragma unroll
    for (int i = 0; i < 8; ++i) {
        const int m = bm + ty * 8 + i;
        const int n = bn + tx * 4;
        float vv[4];
        #pragma unroll
        for (int j = 0; j < 4; ++j) {
            float v = acc[i][j];
            if (EPI == 0) {
                v *= alpha;
            } else if (EPI == 1) {
                v = v + bias[n + j] + res[(long long)m * ldr + n + j];
            } else {
                const float zz = v + bias[n + j];
                v = 0.5f * zz * (1.0f + erff(zz * 0.70710678118654752440f));
            }
            vv[j] = v;
        }
        float4 o;
        o.x = vv[0]; o.y = vv[1]; o.z = vv[2]; o.w = vv[3];
        *(float4*)(C + (long long)m * ldc + n) = o;
    }
}

// ---------------------------------------------------------------------------
// Launch sequence (graph-capturable: kernel launches only)
// ---------------------------------------------------------------------------
extern "C" void kernel_launch(void* const* d_in, const int* in_sizes, int n_in,
                              void* d_out, int out_size)
{
    const float* x     = (const float*)d_in[0];
    const float* y     = (const float*)d_in[1];
    const float* Wq    = (const float*)d_in[2];
    const float* Wk    = (const float*)d_in[3];
    const float* Wv    = (const float*)d_in[4];
    const float* li1_w = (const float*)d_in[5];
    const float* li1_b = (const float*)d_in[6];
    const float* ln1_w = (const float*)d_in[7];
    const float* ln1_b = (const float*)d_in[8];
    const float* ln2_w = (const float*)d_in[9];
    const float* ln2_b = (const float*)d_in[10];
    const float* ln3_w = (const float*)d_in[11];
    const float* ln3_b = (const float*)d_in[12];
    const float* li2_w = (const float*)d_in[13];
    const float* li2_b = (const float*)d_in[14];
    const float* li3_w = (const float*)d_in[15];
    const float* li3_b = (const float*)d_in[16];
    float* out = (float*)d_out;

    float *xn, *yn, *wqp, *wkp, *wvp, *qb, *kb, *vb, *pb, *ob, *xo, *h1, *h2;
    cudaGetSymbolAddress((void**)&xn,  g_xn);
    cudaGetSymbolAddress((void**)&yn,  g_yn);
    cudaGetSymbolAddress((void**)&wqp, g_wqp);
    cudaGetSymbolAddress((void**)&wkp, g_wkp);
    cudaGetSymbolAddress((void**)&wvp, g_wvp);
    cudaGetSymbolAddress((void**)&qb,  g_q);
    cudaGetSymbolAddress((void**)&kb,  g_k);
    cudaGetSymbolAddress((void**)&vb,  g_v);
    cudaGetSymbolAddress((void**)&pb,  g_p);
    cudaGetSymbolAddress((void**)&ob,  g_o);
    cudaGetSymbolAddress((void**)&xo,  g_xout);
    cudaGetSymbolAddress((void**)&h1,  g_h1);
    cudaGetSymbolAddress((void**)&h2,  g_h2);

    const long long SB = 2048LL * 1024;   // per-batch stride in q/k/v/x layouts
    const long long PS = 2048LL * 2048;   // per-(b,h) stride in score buffer

    // 1) LayerNorms of x and y
    ln_kernel<<<4096, 256>>>(x, ln1_w, ln1_b, xn);
    ln_kernel<<<4096, 256>>>(y, ln2_w, ln2_b, yn);

    // 2) Pack head-projection weights to [C, H*D]
    pack_w_kernel<<<4096, 256>>>(Wq, Wk, Wv);

    // 3) Q/K/V projections: [4096,1024] @ [1024,1024]
    dim3 gProj(1024 / 64, 4096 / 128, 1);
    gemm_kernel<0, false><<<gProj, 256>>>(4096, 1024, 1024,
        xn, 1024, 0, 0,  wqp, 1024, 0, 0,  qb, 1024, 0, 0,
        1.0f, nullptr, nullptr, 0);
    gemm_kernel<0, false><<<gProj, 256>>>(4096, 1024, 1024,
        yn, 1024, 0, 0,  wkp, 1024, 0, 0,  kb, 1024, 0, 0,
        1.0f, nullptr, nullptr, 0);
    gemm_kernel<0, false><<<gProj, 256>>>(4096, 1024, 1024,
        yn, 1024, 0, 0,  wvp, 1024, 0, 0,  vb, 1024, 0, 0,
        1.0f, nullptr, nullptr, 0);

    // 4) Scores: S[z] = 0.125 * Q[z] @ K[z]^T, z = b*16 + h (32 batches)
    dim3 gS(2048 / 64, 2048 / 128, 32);
    gemm_kernel<0, true><<<gS, 256>>>(2048, 2048, 64,
        qb, 1024, SB, 64,
        kb, 1024, SB, 64,
        pb, 2048, 16 * PS, PS,
        0.125f, nullptr, nullptr, 0);

    // 5) Row softmax over all t, then zero t <= s
    softmax_mask_kernel<<<65536, 256>>>();

    // 6) O[z] = P[z] @ V[z] -> concat-head layout [ (b,s), (h,d) ]
    dim3 gO(64 / 64, 2048 / 128, 32);
    gemm_kernel<0, false><<<gO, 256>>>(2048, 64, 2048,
        pb, 2048, 16 * PS, PS,
        vb, 1024, SB, 64,
        ob, 1024, SB, 64,
        1.0f, nullptr, nullptr, 0);

    // 7) x_out = x + O @ li1_w + li1_b
    gemm_kernel<1, false><<<gProj, 256>>>(4096, 1024, 1024,
        ob, 1024, 0, 0,  li1_w, 1024, 0, 0,  xo, 1024, 0, 0,
        1.0f, li1_b, x, 1024);

    // 8) h1 = LN(x_out)
    ln_kernel<<<4096, 256>>>(xo, ln3_w, ln3_b, h1);

    // 9) h2 = gelu(h1 @ li2_w + li2_b)   [4096,1024]@[1024,4096]
    dim3 gUp(4096 / 64, 4096 / 128, 1);
    gemm_kernel<2, false><<<gUp, 256>>>(4096, 4096, 1024,
        h1, 1024, 0, 0,  li2_w, 4096, 0, 0,  h2, 4096, 0, 0,
        1.0f, li2_b, nullptr, 0);

    // 10) out = x_out + h2 @ li3_w + li3_b   [4096,4096]@[4096,1024]
    dim3 gDn(1024 / 64, 4096 / 128, 1);
    gemm_kernel<1, false><<<gDn, 256>>>(4096, 1024, 4096,
        h2, 4096, 0, 0,  li3_w, 1024, 0, 0,  out, 1024, 0, 0,
        1.0f, li3_b, xo, 1024);
}

// round 4
// speedup vs baseline: 2.8618x; 2.8618x over previous
#include <cuda_runtime.h>
#include <math.h>
#include <stdint.h>

// ---------------------------------------------------------------------------
// Problem constants: B=2, S=2048, C1=C2=1024, H=16, D=64, W_EXP=4
//   rows = B*S = 4096
// ---------------------------------------------------------------------------

// ---------------- scratch (static __device__ — allocation-free) ------------
__device__ float g_xn  [4096 * 1024];
__device__ float g_yn  [4096 * 1024];
__device__ float g_wqp [1024 * 1024];
__device__ float g_wkp [1024 * 1024];
__device__ float g_wvp [1024 * 1024];
__device__ float g_w1  [1024 * 1024];
__device__ float g_w2  [1024 * 4096];
__device__ float g_w3  [4096 * 1024];
__device__ float g_q   [4096 * 1024];
__device__ float g_k   [4096 * 1024];
__device__ float g_v   [4096 * 1024];
__device__ float g_p   [134217728];      // [32][2048][2048] scores -> probs
__device__ float g_o   [4096 * 1024];
__device__ float g_xout[4096 * 1024];
__device__ float g_h1  [4096 * 1024];
__device__ float g_h2  [4096 * 4096];

// ---------------------------------------------------------------------------
// helpers
// ---------------------------------------------------------------------------
__device__ __forceinline__ float to_tf32(float x) {
    uint32_t u;
    asm("cvt.rna.tf32.f32 %0, %1;" : "=r"(u) : "f"(x));
    return __uint_as_float(u);
}

__device__ __forceinline__ void cp16(float* smem, const float* g) {
    uint32_t s = (uint32_t)__cvta_generic_to_shared(smem);
    asm volatile("cp.async.cg.shared.global [%0], [%1], 16;" :: "r"(s), "l"(g));
}
__device__ __forceinline__ void cp_commit() { asm volatile("cp.async.commit_group;"); }
__device__ __forceinline__ void cp_wait1()  { asm volatile("cp.async.wait_group 1;"); }
__device__ __forceinline__ void cp_wait0()  { asm volatile("cp.async.wait_group 0;"); }

__device__ __forceinline__ void mma_tf32(float* c, const uint32_t* a, const uint32_t* b) {
    asm volatile(
        "mma.sync.aligned.m16n8k8.row.col.f32.tf32.tf32.f32 "
        "{%0,%1,%2,%3}, {%4,%5,%6,%7}, {%8,%9}, {%0,%1,%2,%3};\n"
        : "+f"(c[0]), "+f"(c[1]), "+f"(c[2]), "+f"(c[3])
        : "r"(a[0]), "r"(a[1]), "r"(a[2]), "r"(a[3]), "r"(b[0]), "r"(b[1]));
}

// ---------------------------------------------------------------------------
// LayerNorm over last dim (C = 1024). Output rounded to tf32 (feeds MMAs only).
// ---------------------------------------------------------------------------
__global__ void ln_kernel(const float* __restrict__ x,
                          const float* __restrict__ w,
                          const float* __restrict__ b,
                          float* __restrict__ out)
{
    __shared__ float shs[8], shq[8];
    const int row = blockIdx.x;
    const float* xr = x + (long long)row * 1024;
    float*       orow = out + (long long)row * 1024;
    const int t = threadIdx.x;

    float4 f = *(const float4*)(xr + t * 4);
    float s = f.x + f.y + f.z + f.w;
    float q = f.x * f.x + f.y * f.y + f.z * f.z + f.w * f.w;
    #pragma unroll
    for (int o = 16; o; o >>= 1) {
        s += __shfl_xor_sync(0xFFFFFFFFu, s, o);
        q += __shfl_xor_sync(0xFFFFFFFFu, q, o);
    }
    const int wid = t >> 5, ln = t & 31;
    if (ln == 0) { shs[wid] = s; shq[wid] = q; }
    __syncthreads();
    if (wid == 0) {
        float a = (ln < 8) ? shs[ln] : 0.0f;
        float c = (ln < 8) ? shq[ln] : 0.0f;
        #pragma unroll
        for (int o = 4; o; o >>= 1) {
            a += __shfl_xor_sync(0xFFFFFFFFu, a, o);
            c += __shfl_xor_sync(0xFFFFFFFFu, c, o);
        }
        if (ln == 0) { shs[0] = a; shq[0] = c; }
    }
    __syncthreads();
    const float mu  = shs[0] * (1.0f / 1024.0f);
    const float var = shq[0] * (1.0f / 1024.0f) - mu * mu;
    const float rs  = rsqrtf(var + 1e-5f);

    float4 wv = *(const float4*)(w + t * 4);
    float4 bv = *(const float4*)(b + t * 4);
    float4 ov;
    ov.x = to_tf32((f.x - mu) * rs * wv.x + bv.x);
    ov.y = to_tf32((f.y - mu) * rs * wv.y + bv.y);
    ov.z = to_tf32((f.z - mu) * rs * wv.z + bv.z);
    ov.w = to_tf32((f.w - mu) * rs * wv.w + bv.w);
    *(float4*)(orow + t * 4) = ov;
}

// ---------------------------------------------------------------------------
// Pack per-head weights [H, C, D] -> [C, H*D], rounded to tf32.
// ---------------------------------------------------------------------------
__global__ void pack_w_kernel(const float* __restrict__ Wq,
                              const float* __restrict__ Wk,
                              const float* __restrict__ Wv)
{
    const int i = blockIdx.x * 256 + threadIdx.x;   // 0 .. 1M-1
    const int c = i >> 10;
    const int j = i & 1023;
    const int h = j >> 6;
    const int d = j & 63;
    const int src = h * 65536 + c * 64 + d;
    g_wqp[i] = to_tf32(Wq[src]);
    g_wkp[i] = to_tf32(Wk[src]);
    g_wvp[i] = to_tf32(Wv[src]);
}

// ---------------------------------------------------------------------------
// Round fp32 weights to tf32 into scratch (vectorized).
// ---------------------------------------------------------------------------
__global__ void round_tf32_kernel(const float* __restrict__ src,
                                  float* __restrict__ dst, int n4)
{
    const int i = blockIdx.x * 256 + threadIdx.x;
    if (i < n4) {
        float4 f = *(const float4*)(src + i * 4);
        f.x = to_tf32(f.x); f.y = to_tf32(f.y);
        f.z = to_tf32(f.z); f.w = to_tf32(f.w);
        *(float4*)(dst + i * 4) = f;
    }
}

// ---------------------------------------------------------------------------
// Full-row softmax over 2048 cols, then zero entries with t <= s. In-place.
// Output rounded to tf32 (feeds PV MMA).
// ---------------------------------------------------------------------------
__global__ void softmax_mask_kernel()
{
    __shared__ float sh[8];
    const long long row = blockIdx.x;
    const int s = (int)(row & 2047);
    float* p = g_p + row * 2048;
    const int t = threadIdx.x;
    const int t0 = t * 8;

    float4 f1 = *(const float4*)(p + t0);
    float4 f2 = *(const float4*)(p + t0 + 4);
    float v[8] = {f1.x, f1.y, f1.z, f1.w, f2.x, f2.y, f2.z, f2.w};

    float mx = v[0];
    #pragma unroll
    for (int j = 1; j < 8; ++j) mx = fmaxf(mx, v[j]);
    #pragma unroll
    for (int o = 16; o; o >>= 1) mx = fmaxf(mx, __shfl_xor_sync(0xFFFFFFFFu, mx, o));
    const int wid = t >> 5, ln = t & 31;
    if (ln == 0) sh[wid] = mx;
    __syncthreads();
    if (wid == 0) {
        float a = (ln < 8) ? sh[ln] : -3.0e38f;
        #pragma unroll
        for (int o = 4; o; o >>= 1) a = fmaxf(a, __shfl_xor_sync(0xFFFFFFFFu, a, o));
        if (ln == 0) sh[0] = a;
    }
    __syncthreads();
    const float M = sh[0];
    __syncthreads();

    float e[8];
    float sum = 0.0f;
    #pragma unroll
    for (int j = 0; j < 8; ++j) { e[j] = __expf(v[j] - M); sum += e[j]; }
    #pragma unroll
    for (int o = 16; o; o >>= 1) sum += __shfl_xor_sync(0xFFFFFFFFu, sum, o);
    if (ln == 0) sh[wid] = sum;
    __syncthreads();
    if (wid == 0) {
        float a = (ln < 8) ? sh[ln] : 0.0f;
        #pragma unroll
        for (int o = 4; o; o >>= 1) a += __shfl_xor_sync(0xFFFFFFFFu, a, o);
        if (ln == 0) sh[0] = a;
    }
    __syncthreads();
    const float inv = 1.0f / sh[0];

    float r[8];
    #pragma unroll
    for (int j = 0; j < 8; ++j) r[j] = (t0 + j > s) ? to_tf32(e[j] * inv) : 0.0f;
    float4 o1, o2;
    o1.x = r[0]; o1.y = r[1]; o1.z = r[2]; o1.w = r[3];
    o2.x = r[4]; o2.y = r[5]; o2.z = r[6]; o2.w = r[7];
    *(float4*)(p + t0)     = o1;
    *(float4*)(p + t0 + 4) = o2;
}

// ---------------------------------------------------------------------------
// Tensor-core tf32 GEMM.  BM=128, BK=16, BN in {128, 64}.  256 threads =
// 8 warps laid out WARPS_M x WARPS_N; each warp computes (BM/WARPS_M) x
// (BN/WARPS_N) via m16n8k8 tf32 mma.sync.  cp.async double buffering.
//
// Smem layouts (conflict-free for the mma fragment patterns):
//   As[m][20]            (row-major, k-stride 1, pad row to 20 floats)
//   Bs[k][BN+8]          (non-trans: B gmem is [K][N])
//   Bs[n][20]            (TRANSB:    B gmem is [N][K])
//
// EPI: 0 = alpha*acc ; 1 = acc + bias[n] + res[m][n] ; 2 = gelu(acc + bias[n])
// CVT: round result to tf32 (when the output feeds another MMA).
// Batch z: operand offset = (z>>4)*SB + (z&15)*SH.
// ---------------------------------------------------------------------------
template<int BN, int WARPS_M, int WARPS_N, bool TRANSB, int EPI, bool CVT>
__global__ __launch_bounds__(256, 2)
void gemm_tc(int M, int N, int K,
             const float* __restrict__ A, int lda, long long aSB, long long aSH,
             const float* __restrict__ B, int ldb, long long bSB, long long bSH,
             float* __restrict__ C, int ldc, long long cSB, long long cSH,
             float alpha,
             const float* __restrict__ bias,
             const float* __restrict__ res, int ldr)
{
    constexpr int BM = 128, BK = 16;
    constexpr int WM = BM / WARPS_M, WN = BN / WARPS_N;
    constexpr int MT = WM / 16, NT = WN / 8;
    constexpr int BNP = BN + 8;
    constexpr int BSZ = TRANSB ? BN * 20 : BK * BNP;

    __shared__ float As[2][BM * 20];
    __shared__ float Bs[2][BSZ];

    const int z  = blockIdx.z;
    const long long zb = z >> 4, zh = z & 15;
    A += zb * aSB + zh * aSH;
    B += zb * bSB + zh * bSH;
    C += zb * cSB + zh * cSH;

    const int bm = blockIdx.y * BM;
    const int bn = blockIdx.x * BN;
    const int t    = threadIdx.x;
    const int warp = t >> 5;
    const int lane = t & 31;
    const int g  = lane >> 2;      // group id (0..7)
    const int tg = lane & 3;       // thread in group (0..3)
    const int wmBase = (warp / WARPS_N) * WM;
    const int wnBase = (warp % WARPS_N) * WN;

    float acc[MT][NT][4];
    #pragma unroll
    for (int i = 0; i < MT; ++i)
        #pragma unroll
        for (int j = 0; j < NT; ++j)
            #pragma unroll
            for (int q = 0; q < 4; ++q) acc[i][j][q] = 0.0f;

    // ---- async tile loaders ----
    auto loadA = [&](int kt, int buf) {
        const float* Ag = A + (long long)bm * lda + kt * BK;
        #pragma unroll
        for (int i = 0; i < 2; ++i) {
            const int id = t + i * 256;            // 512 16B chunks
            const int m = id >> 2, kc = id & 3;
            cp16(&As[buf][m * 20 + kc * 4], Ag + (long long)m * lda + kc * 4);
        }
    };
    auto loadB = [&](int kt, int buf) {
        if (TRANSB) {
            const float* Bg = B + (long long)bn * ldb + kt * BK;
            #pragma unroll
            for (int i = 0; i < (BN * 4) / 256; ++i) {
                const int id = t + i * 256;
                const int n = id >> 2, kc = id & 3;
                cp16(&Bs[buf][n * 20 + kc * 4], Bg + (long long)n * ldb + kc * 4);
            }
        } else {
            const float* Bg = B + (long long)(kt * BK) * ldb + bn;
            #pragma unroll
            for (int i = 0; i < (BK * (BN / 4)) / 256; ++i) {
                const int id = t + i * 256;
                const int k = id / (BN / 4), nc = id % (BN / 4);
                cp16(&Bs[buf][k * BNP + nc * 4], Bg + (long long)k * ldb + nc * 4);
            }
        }
    };

    const int nk = K / BK;
    loadA(0, 0); loadB(0, 0); cp_commit();

    for (int kt = 0; kt < nk; ++kt) {
        const int buf = kt & 1;
        if (kt + 1 < nk) {
            loadA(kt + 1, buf ^ 1); loadB(kt + 1, buf ^ 1); cp_commit();
            cp_wait1();
        } else {
            cp_wait0();
        }
        __syncthreads();

        #pragma unroll
        for (int ks = 0; ks < 2; ++ks) {
            const int k0 = ks * 8;
            uint32_t a[MT][4], b[NT][2];
            #pragma unroll
            for (int mt = 0; mt < MT; ++mt) {
                const int m = wmBase + mt * 16 + g;
                const float* p = &As[buf][m * 20 + k0 + tg];
                a[mt][0] = __float_as_uint(p[0]);
                a[mt][1] = __float_as_uint(p[8 * 20]);
                a[mt][2] = __float_as_uint(p[4]);
                a[mt][3] = __float_as_uint(p[8 * 20 + 4]);
            }
            #pragma unroll
            for (int nt = 0; nt < NT; ++nt) {
                const int n = wnBase + nt * 8 + g;
                if (TRANSB) {
                    const float* p = &Bs[buf][n * 20 + k0 + tg];
                    b[nt][0] = __float_as_uint(p[0]);
                    b[nt][1] = __float_as_uint(p[4]);
                } else {
                    const float* p = &Bs[buf][(k0 + tg) * BNP + n];
                    b[nt][0] = __float_as_uint(p[0]);
                    b[nt][1] = __float_as_uint(p[4 * BNP]);
                }
            }
            #pragma unroll
            for (int mt = 0; mt < MT; ++mt)
                #pragma unroll
                for (int nt = 0; nt < NT; ++nt)
                    mma_tf32(acc[mt][nt], a[mt], b[nt]);
        }
        __syncthreads();
    }

    // ---- epilogue ----
    #pragma unroll
    for (int mt = 0; mt < MT; ++mt) {
        #pragma unroll
        for (int nt = 0; nt < NT; ++nt) {
            const int r0 = bm + wmBase + mt * 16 + g;
            const int c0 = bn + wnBase + nt * 8 + tg * 2;
            #pragma unroll
            for (int half = 0; half < 2; ++half) {
                const int r = r0 + half * 8;
                float v0 = acc[mt][nt][half * 2 + 0];
                float v1 = acc[mt][nt][half * 2 + 1];
                if (EPI == 0) {
                    v0 *= alpha; v1 *= alpha;
                } else if (EPI == 1) {
                    v0 += bias[c0]     + res[(long long)r * ldr + c0];
                    v1 += bias[c0 + 1] + res[(long long)r * ldr + c0 + 1];
                } else {
                    const float z0 = v0 + bias[c0];
                    const float z1 = v1 + bias[c0 + 1];
                    v0 = 0.5f * z0 * (1.0f + erff(z0 * 0.70710678118654752440f));
                    v1 = 0.5f * z1 * (1.0f + erff(z1 * 0.70710678118654752440f));
                }
                if (CVT) { v0 = to_tf32(v0); v1 = to_tf32(v1); }
                float2 o; o.x = v0; o.y = v1;
                *(float2*)(C + (long long)r * ldc + c0) = o;
            }
        }
    }
}

// ---------------------------------------------------------------------------
// Launch sequence (graph-capturable: kernel launches only)
// ---------------------------------------------------------------------------
extern "C" void kernel_launch(void* const* d_in, const int* in_sizes, int n_in,
                              void* d_out, int out_size)
{
    const float* x     = (const float*)d_in[0];
    const float* y     = (const float*)d_in[1];
    const float* Wq    = (const float*)d_in[2];
    const float* Wk    = (const float*)d_in[3];
    const float* Wv    = (const float*)d_in[4];
    const float* li1_w = (const float*)d_in[5];
    const float* li1_b = (const float*)d_in[6];
    const float* ln1_w = (const float*)d_in[7];
    const float* ln1_b = (const float*)d_in[8];
    const float* ln2_w = (const float*)d_in[9];
    const float* ln2_b = (const float*)d_in[10];
    const float* ln3_w = (const float*)d_in[11];
    const float* ln3_b = (const float*)d_in[12];
    const float* li2_w = (const float*)d_in[13];
    const float* li2_b = (const float*)d_in[14];
    const float* li3_w = (const float*)d_in[15];
    const float* li3_b = (const float*)d_in[16];
    float* out = (float*)d_out;

    float *xn, *yn, *wqp, *wkp, *wvp, *w1, *w2, *w3;
    float *qb, *kb, *vb, *pb, *ob, *xo, *h1, *h2;
    cudaGetSymbolAddress((void**)&xn,  g_xn);
    cudaGetSymbolAddress((void**)&yn,  g_yn);
    cudaGetSymbolAddress((void**)&wqp, g_wqp);
    cudaGetSymbolAddress((void**)&wkp, g_wkp);
    cudaGetSymbolAddress((void**)&wvp, g_wvp);
    cudaGetSymbolAddress((void**)&w1,  g_w1);
    cudaGetSymbolAddress((void**)&w2,  g_w2);
    cudaGetSymbolAddress((void**)&w3,  g_w3);
    cudaGetSymbolAddress((void**)&qb,  g_q);
    cudaGetSymbolAddress((void**)&kb,  g_k);
    cudaGetSymbolAddress((void**)&vb,  g_v);
    cudaGetSymbolAddress((void**)&pb,  g_p);
    cudaGetSymbolAddress((void**)&ob,  g_o);
    cudaGetSymbolAddress((void**)&xo,  g_xout);
    cudaGetSymbolAddress((void**)&h1,  g_h1);
    cudaGetSymbolAddress((void**)&h2,  g_h2);

    const long long SB = 2048LL * 1024;   // per-batch stride in q/k/v layouts
    const long long PS = 2048LL * 2048;   // per-(b,h) stride in score buffer

    // 1) LayerNorms of x and y (outputs tf32-rounded)
    ln_kernel<<<4096, 256>>>(x, ln1_w, ln1_b, xn);
    ln_kernel<<<4096, 256>>>(y, ln2_w, ln2_b, yn);

    // 2) Pack head weights to [C, H*D] (tf32) + round linear weights (tf32)
    pack_w_kernel<<<4096, 256>>>(Wq, Wk, Wv);
    round_tf32_kernel<<<1024, 256>>>(li1_w, w1, 1024 * 1024 / 4);
    round_tf32_kernel<<<4096, 256>>>(li2_w, w2, 1024 * 4096 / 4);
    round_tf32_kernel<<<4096, 256>>>(li3_w, w3, 4096 * 1024 / 4);

    // 3) Q/K/V projections: [4096,1024] @ [1024,1024]
    dim3 gProj(1024 / 128, 4096 / 128, 1);
    gemm_tc<128, 2, 4, false, 0, true><<<gProj, 256>>>(4096, 1024, 1024,
        xn, 1024, 0, 0,  wqp, 1024, 0, 0,  qb, 1024, 0, 0,
        1.0f, nullptr, nullptr, 0);
    gemm_tc<128, 2, 4, false, 0, true><<<gProj, 256>>>(4096, 1024, 1024,
        yn, 1024, 0, 0,  wkp, 1024, 0, 0,  kb, 1024, 0, 0,
        1.0f, nullptr, nullptr, 0);
    gemm_tc<128, 2, 4, false, 0, true><<<gProj, 256>>>(4096, 1024, 1024,
        yn, 1024, 0, 0,  wvp, 1024, 0, 0,  vb, 1024, 0, 0,
        1.0f, nullptr, nullptr, 0);

    // 4) Scores: S[z] = 0.125 * Q[z] @ K[z]^T, z = b*16 + h
    dim3 gS(2048 / 128, 2048 / 128, 32);
    gemm_tc<128, 2, 4, true, 0, false><<<gS, 256>>>(2048, 2048, 64,
        qb, 1024, SB, 64,
        kb, 1024, SB, 64,
        pb, 2048, 16 * PS, PS,
        0.125f, nullptr, nullptr, 0);

    // 5) Row softmax over all t, then zero t <= s (tf32-rounded probs)
    softmax_mask_kernel<<<65536, 256>>>();

    // 6) O[z] = P[z] @ V[z] -> concat-head layout [(b,s), (h,d)]
    dim3 gO(64 / 64, 2048 / 128, 32);
    gemm_tc<64, 4, 2, false, 0, true><<<gO, 256>>>(2048, 64, 2048,
        pb, 2048, 16 * PS, PS,
        vb, 1024, SB, 64,
        ob, 1024, SB, 64,
        1.0f, nullptr, nullptr, 0);

    // 7) x_out = x + O @ li1_w + li1_b (full fp32 output)
    gemm_tc<128, 2, 4, false, 1, false><<<gProj, 256>>>(4096, 1024, 1024,
        ob, 1024, 0, 0,  w1, 1024, 0, 0,  xo, 1024, 0, 0,
        1.0f, li1_b, x, 1024);

    // 8) h1 = LN(x_out) (tf32-rounded)
    ln_kernel<<<4096, 256>>>(xo, ln3_w, ln3_b, h1);

    // 9) h2 = gelu(h1 @ li2_w + li2_b)  [4096,1024]@[1024,4096] (tf32-rounded)
    dim3 gUp(4096 / 128, 4096 / 128, 1);
    gemm_tc<128, 2, 4, false, 2, true><<<gUp, 256>>>(4096, 4096, 1024,
        h1, 1024, 0, 0,  w2, 4096, 0, 0,  h2, 4096, 0, 0,
        1.0f, li2_b, nullptr, 0);

    // 10) out = x_out + h2 @ li3_w + li3_b  [4096,4096]@[4096,1024]
    dim3 gDn(1024 / 128, 4096 / 128, 1);
    gemm_tc<128, 2, 4, false, 1, false><<<gDn, 256>>>(4096, 1024, 4096,
        h2, 4096, 0, 0,  w3, 1024, 0, 0,  out, 1024, 0, 0,
        1.0f, li3_b, xo, 1024);
}

// round 5
// speedup vs baseline: 3.3526x; 1.1715x over previous
#include <cuda_runtime.h>
#include <math.h>
#include <stdint.h>

// ---------------------------------------------------------------------------
// Problem constants: B=2, S=2048, C1=C2=1024, H=16, D=64, W_EXP=4
//   rows = B*S = 4096
// ---------------------------------------------------------------------------

// ---------------- scratch (static __device__ — allocation-free) ------------
__device__ float g_xn  [4096 * 1024];
__device__ float g_yn  [4096 * 1024];
__device__ float g_wqp [1024 * 1024];
__device__ float g_wkp [1024 * 1024];
__device__ float g_wvp [1024 * 1024];
__device__ float g_w1  [1024 * 1024];
__device__ float g_w2  [1024 * 4096];
__device__ float g_w3  [4096 * 1024];
__device__ float g_q   [4096 * 1024];
__device__ float g_k   [4096 * 1024];
__device__ float g_v   [4096 * 1024];
__device__ float g_o   [4096 * 1024];
__device__ float g_xout[4096 * 1024];
__device__ float g_h1  [4096 * 1024];
__device__ float g_h2  [4096 * 4096];

// ---------------------------------------------------------------------------
// helpers
// ---------------------------------------------------------------------------
__device__ __forceinline__ float to_tf32(float x) {
    uint32_t u;
    asm("cvt.rna.tf32.f32 %0, %1;" : "=r"(u) : "f"(x));
    return __uint_as_float(u);
}

__device__ __forceinline__ void cp16(float* smem, const float* g) {
    uint32_t s = (uint32_t)__cvta_generic_to_shared(smem);
    asm volatile("cp.async.cg.shared.global [%0], [%1], 16;" :: "r"(s), "l"(g));
}
__device__ __forceinline__ void cp_commit() { asm volatile("cp.async.commit_group;"); }
__device__ __forceinline__ void cp_wait2()  { asm volatile("cp.async.wait_group 2;"); }
__device__ __forceinline__ void cp_wait1()  { asm volatile("cp.async.wait_group 1;"); }
__device__ __forceinline__ void cp_wait0()  { asm volatile("cp.async.wait_group 0;"); }

__device__ __forceinline__ void mma_tf32(float* c, const uint32_t* a, const uint32_t* b) {
    asm volatile(
        "mma.sync.aligned.m16n8k8.row.col.f32.tf32.tf32.f32 "
        "{%0,%1,%2,%3}, {%4,%5,%6,%7}, {%8,%9}, {%0,%1,%2,%3};\n"
        : "+f"(c[0]), "+f"(c[1]), "+f"(c[2]), "+f"(c[3])
        : "r"(a[0]), "r"(a[1]), "r"(a[2]), "r"(a[3]), "r"(b[0]), "r"(b[1]));
}

// ---------------------------------------------------------------------------
// LayerNorm over last dim (C = 1024). Output rounded to tf32 (feeds MMAs only).
// ---------------------------------------------------------------------------
__global__ void ln_kernel(const float* __restrict__ x,
                          const float* __restrict__ w,
                          const float* __restrict__ b,
                          float* __restrict__ out)
{
    __shared__ float shs[8], shq[8];
    const int row = blockIdx.x;
    const float* xr = x + (long long)row * 1024;
    float*       orow = out + (long long)row * 1024;
    const int t = threadIdx.x;

    float4 f = *(const float4*)(xr + t * 4);
    float s = f.x + f.y + f.z + f.w;
    float q = f.x * f.x + f.y * f.y + f.z * f.z + f.w * f.w;
    #pragma unroll
    for (int o = 16; o; o >>= 1) {
        s += __shfl_xor_sync(0xFFFFFFFFu, s, o);
        q += __shfl_xor_sync(0xFFFFFFFFu, q, o);
    }
    const int wid = t >> 5, ln = t & 31;
    if (ln == 0) { shs[wid] = s; shq[wid] = q; }
    __syncthreads();
    if (wid == 0) {
        float a = (ln < 8) ? shs[ln] : 0.0f;
        float c = (ln < 8) ? shq[ln] : 0.0f;
        #pragma unroll
        for (int o = 4; o; o >>= 1) {
            a += __shfl_xor_sync(0xFFFFFFFFu, a, o);
            c += __shfl_xor_sync(0xFFFFFFFFu, c, o);
        }
        if (ln == 0) { shs[0] = a; shq[0] = c; }
    }
    __syncthreads();
    const float mu  = shs[0] * (1.0f / 1024.0f);
    const float var = shq[0] * (1.0f / 1024.0f) - mu * mu;
    const float rs  = rsqrtf(var + 1e-5f);

    float4 wv = *(const float4*)(w + t * 4);
    float4 bv = *(const float4*)(b + t * 4);
    float4 ov;
    ov.x = to_tf32((f.x - mu) * rs * wv.x + bv.x);
    ov.y = to_tf32((f.y - mu) * rs * wv.y + bv.y);
    ov.z = to_tf32((f.z - mu) * rs * wv.z + bv.z);
    ov.w = to_tf32((f.w - mu) * rs * wv.w + bv.w);
    *(float4*)(orow + t * 4) = ov;
}

// ---------------------------------------------------------------------------
// Pack per-head weights [H, C, D] -> [C, H*D], rounded to tf32.
// ---------------------------------------------------------------------------
__global__ void pack_w_kernel(const float* __restrict__ Wq,
                              const float* __restrict__ Wk,
                              const float* __restrict__ Wv)
{
    const int i = blockIdx.x * 256 + threadIdx.x;   // 0 .. 1M-1
    const int c = i >> 10;
    const int j = i & 1023;
    const int h = j >> 6;
    const int d = j & 63;
    const int src = h * 65536 + c * 64 + d;
    g_wqp[i] = to_tf32(Wq[src]);
    g_wkp[i] = to_tf32(Wk[src]);
    g_wvp[i] = to_tf32(Wv[src]);
}

// ---------------------------------------------------------------------------
// Round fp32 weights to tf32 into scratch (vectorized).
// ---------------------------------------------------------------------------
__global__ void round_tf32_kernel(const float* __restrict__ src,
                                  float* __restrict__ dst, int n4)
{
    const int i = blockIdx.x * 256 + threadIdx.x;
    if (i < n4) {
        float4 f = *(const float4*)(src + i * 4);
        f.x = to_tf32(f.x); f.y = to_tf32(f.y);
        f.z = to_tf32(f.z); f.w = to_tf32(f.w);
        *(float4*)(dst + i * 4) = f;
    }
}

// ---------------------------------------------------------------------------
// Fused flash attention with post-softmax masking.
//   O_s = (1/sum_all_t exp(s_t - m)) * sum_{t>s} exp(s_t - m) v_t
// Online softmax: l accumulates over ALL t; P used for PV is masked.
// Per CTA: one (z, 128-row) block. 8 warps x 16 rows. D=64, t-tiles of 64.
// Q kept in registers (pre-scaled by 0.125). K/V double-buffered cp.async.
// P routed through smem (warp-private rows -> __syncwarp only).
// smem: sP[128][68] (also Q staging) | sK[2][64][68] | sV[2][64][72] = 104KB.
// ---------------------------------------------------------------------------
#define FA_SMEM_BYTES (128*68*4 + 2*64*68*4 + 2*64*72*4)   // 106496

__global__ __launch_bounds__(256)
void flash_attn_kernel(const float* __restrict__ Qg,
                       const float* __restrict__ Kg,
                       const float* __restrict__ Vg,
                       float* __restrict__ Og)
{
    extern __shared__ float sm[];
    float* sP = sm;                         // [128][68]
    float* sK = sm + 128 * 68;              // [2][64*68]
    float* sV = sm + 128 * 68 + 2 * 64 * 68;// [2][64*72]

    const int z = blockIdx.z;
    const long long zb = z >> 4, zh = z & 15;
    const long long base = zb * (2048LL * 1024) + zh * 64;
    const float* Qp = Qg + base;
    const float* Kp = Kg + base;
    const float* Vp = Vg + base;

    const int bm = blockIdx.y * 128;
    const int t = threadIdx.x;
    const int w = t >> 5, lane = t & 31, g = lane >> 2, tg = lane & 3;

    // ---- stage Q tile into sP ----
    {
        const float* Qa = Qp + (long long)bm * 1024;
        #pragma unroll
        for (int i = 0; i < 8; ++i) {
            const int id = t + i * 256;         // 2048 chunks of 16B
            const int m = id >> 4, c = id & 15;
            cp16(&sP[m * 68 + c * 4], Qa + (long long)m * 1024 + c * 4);
        }
        cp_commit();
    }

    auto loadKV = [&](int it, int buf) {
        const float* Ka = Kp + (long long)(it * 64) * 1024;
        const float* Va = Vp + (long long)(it * 64) * 1024;
        #pragma unroll
        for (int i = 0; i < 4; ++i) {
            const int id = t + i * 256;         // 1024 chunks
            const int r = id >> 4, c = id & 15;
            cp16(&sK[buf * (64 * 68) + r * 68 + c * 4], Ka + (long long)r * 1024 + c * 4);
        }
        #pragma unroll
        for (int i = 0; i < 4; ++i) {
            const int id = t + i * 256;
            const int r = id >> 4, c = id & 15;
            cp16(&sV[buf * (64 * 72) + r * 72 + c * 4], Va + (long long)r * 1024 + c * 4);
        }
        cp_commit();
    };
    loadKV(0, 0);
    loadKV(1, 1);

    cp_wait2();                 // Q group done (K0/V0, K1/V1 may be pending)
    __syncthreads();

    // ---- Q fragments (x 0.125 == D^-0.5, exact on tf32) ----
    uint32_t aq[8][4];
    {
        const int m = w * 16 + g;
        #pragma unroll
        for (int kk = 0; kk < 8; ++kk) {
            const float* p = &sP[m * 68 + kk * 8 + tg];
            aq[kk][0] = __float_as_uint(p[0]          * 0.125f);
            aq[kk][1] = __float_as_uint(p[8 * 68]     * 0.125f);
            aq[kk][2] = __float_as_uint(p[4]          * 0.125f);
            aq[kk][3] = __float_as_uint(p[8 * 68 + 4] * 0.125f);
        }
    }
    // (loop's first __syncthreads orders these reads before any sP overwrite)

    float accO[8][4];
    #pragma unroll
    for (int i = 0; i < 8; ++i)
        #pragma unroll
        for (int j = 0; j < 4; ++j) accO[i][j] = 0.0f;
    float m0 = -1e30f, m1 = -1e30f, l0 = 0.0f, l1 = 0.0f;

    const int srow0 = bm + w * 16 + g;
    const int srow1 = srow0 + 8;

    for (int it = 0; it < 32; ++it) {
        const int buf = it & 1;
        if (it + 1 < 32) cp_wait1(); else cp_wait0();
        __syncthreads();

        // ---- S = (Q * 0.125) K^T ----
        float s[8][4];
        #pragma unroll
        for (int i = 0; i < 8; ++i) { s[i][0]=0; s[i][1]=0; s[i][2]=0; s[i][3]=0; }
        const float* Kb = &sK[buf * (64 * 68)];
        #pragma unroll
        for (int kk = 0; kk < 8; ++kk) {
            #pragma unroll
            for (int nt = 0; nt < 8; ++nt) {
                uint32_t b[2];
                const float* p = &Kb[(nt * 8 + g) * 68 + kk * 8 + tg];
                b[0] = __float_as_uint(p[0]);
                b[1] = __float_as_uint(p[4]);
                mma_tf32(s[nt], aq[kk], b);
            }
        }

        // ---- online softmax (l over ALL t; mask applies to P only) ----
        float tmax0 = s[0][0], tmax1 = s[0][2];
        #pragma unroll
        for (int nt = 0; nt < 8; ++nt) {
            tmax0 = fmaxf(tmax0, fmaxf(s[nt][0], s[nt][1]));
            tmax1 = fmaxf(tmax1, fmaxf(s[nt][2], s[nt][3]));
        }
        tmax0 = fmaxf(tmax0, __shfl_xor_sync(0xFFFFFFFFu, tmax0, 1));
        tmax0 = fmaxf(tmax0, __shfl_xor_sync(0xFFFFFFFFu, tmax0, 2));
        tmax1 = fmaxf(tmax1, __shfl_xor_sync(0xFFFFFFFFu, tmax1, 1));
        tmax1 = fmaxf(tmax1, __shfl_xor_sync(0xFFFFFFFFu, tmax1, 2));
        const float mn0 = fmaxf(m0, tmax0), mn1 = fmaxf(m1, tmax1);
        const float al0 = __expf(m0 - mn0), al1 = __expf(m1 - mn1);
        float ls0 = 0.0f, ls1 = 0.0f;
        #pragma unroll
        for (int nt = 0; nt < 8; ++nt) {
            s[nt][0] = __expf(s[nt][0] - mn0); ls0 += s[nt][0];
            s[nt][1] = __expf(s[nt][1] - mn0); ls0 += s[nt][1];
            s[nt][2] = __expf(s[nt][2] - mn1); ls1 += s[nt][2];
            s[nt][3] = __expf(s[nt][3] - mn1); ls1 += s[nt][3];
        }
        ls0 += __shfl_xor_sync(0xFFFFFFFFu, ls0, 1);
        ls0 += __shfl_xor_sync(0xFFFFFFFFu, ls0, 2);
        ls1 += __shfl_xor_sync(0xFFFFFFFFu, ls1, 1);
        ls1 += __shfl_xor_sync(0xFFFFFFFFu, ls1, 2);
        l0 = l0 * al0 + ls0;  l1 = l1 * al1 + ls1;
        m0 = mn0;  m1 = mn1;
        #pragma unroll
        for (int nt = 0; nt < 8; ++nt) {
            accO[nt][0] *= al0; accO[nt][1] *= al0;
            accO[nt][2] *= al1; accO[nt][3] *= al1;
        }

        // ---- masked tf32 P -> sP (warp-private rows) ----
        const int tbase = it * 64;
        #pragma unroll
        for (int nt = 0; nt < 8; ++nt) {
            const int tc = tbase + nt * 8 + 2 * tg;
            float2 v01, v23;
            v01.x = (tc     > srow0) ? to_tf32(s[nt][0]) : 0.0f;
            v01.y = (tc + 1 > srow0) ? to_tf32(s[nt][1]) : 0.0f;
            v23.x = (tc     > srow1) ? to_tf32(s[nt][2]) : 0.0f;
            v23.y = (tc + 1 > srow1) ? to_tf32(s[nt][3]) : 0.0f;
            *(float2*)&sP[(w * 16 + g)     * 68 + nt * 8 + 2 * tg] = v01;
            *(float2*)&sP[(w * 16 + g + 8) * 68 + nt * 8 + 2 * tg] = v23;
        }
        __syncwarp();

        // ---- O += P V ----
        const float* Vb = &sV[buf * (64 * 72)];
        #pragma unroll
        for (int kk = 0; kk < 8; ++kk) {
            uint32_t a[4];
            const float* pa = &sP[(w * 16 + g) * 68 + kk * 8 + tg];
            a[0] = __float_as_uint(pa[0]);
            a[1] = __float_as_uint(pa[8 * 68]);
            a[2] = __float_as_uint(pa[4]);
            a[3] = __float_as_uint(pa[8 * 68 + 4]);
            #pragma unroll
            for (int nt = 0; nt < 8; ++nt) {
                uint32_t b[2];
                const float* pb2 = &Vb[(kk * 8 + tg) * 72 + nt * 8 + g];
                b[0] = __float_as_uint(pb2[0]);
                b[1] = __float_as_uint(pb2[4 * 72]);
                mma_tf32(accO[nt], a, b);
            }
        }
        __syncthreads();
        if (it + 2 < 32) loadKV(it + 2, buf);
    }

    // ---- epilogue: O /= l (l >= 1 always), write concat-head layout ----
    const float inv0 = 1.0f / l0, inv1 = 1.0f / l1;
    float* Ob = Og + zb * (2048LL * 1024) + zh * 64;
    #pragma unroll
    for (int nt = 0; nt < 8; ++nt) {
        const int c = nt * 8 + 2 * tg;
        float2 v01, v23;
        v01.x = to_tf32(accO[nt][0] * inv0);
        v01.y = to_tf32(accO[nt][1] * inv0);
        v23.x = to_tf32(accO[nt][2] * inv1);
        v23.y = to_tf32(accO[nt][3] * inv1);
        *(float2*)(Ob + (long long)srow0 * 1024 + c) = v01;
        *(float2*)(Ob + (long long)srow1 * 1024 + c) = v23;
    }
}

// ---------------------------------------------------------------------------
// Tensor-core tf32 GEMM (unchanged from R4).  BM=128, BK=16, BN=128.
// EPI: 0 = alpha*acc ; 1 = acc + bias[n] + res[m][n] ; 2 = gelu(acc + bias[n])
// ---------------------------------------------------------------------------
template<int BN, int WARPS_M, int WARPS_N, bool TRANSB, int EPI, bool CVT>
__global__ __launch_bounds__(256, 2)
void gemm_tc(int M, int N, int K,
             const float* __restrict__ A, int lda, long long aSB, long long aSH,
             const float* __restrict__ B, int ldb, long long bSB, long long bSH,
             float* __restrict__ C, int ldc, long long cSB, long long cSH,
             float alpha,
             const float* __restrict__ bias,
             const float* __restrict__ res, int ldr)
{
    constexpr int BM = 128, BK = 16;
    constexpr int WM = BM / WARPS_M, WN = BN / WARPS_N;
    constexpr int MT = WM / 16, NT = WN / 8;
    constexpr int BNP = BN + 8;
    constexpr int BSZ = TRANSB ? BN * 20 : BK * BNP;

    __shared__ float As[2][BM * 20];
    __shared__ float Bs[2][BSZ];

    const int z  = blockIdx.z;
    const long long zb = z >> 4, zh = z & 15;
    A += zb * aSB + zh * aSH;
    B += zb * bSB + zh * bSH;
    C += zb * cSB + zh * cSH;

    const int bm = blockIdx.y * BM;
    const int bn = blockIdx.x * BN;
    const int t    = threadIdx.x;
    const int warp = t >> 5;
    const int lane = t & 31;
    const int g  = lane >> 2;
    const int tg = lane & 3;
    const int wmBase = (warp / WARPS_N) * WM;
    const int wnBase = (warp % WARPS_N) * WN;

    float acc[MT][NT][4];
    #pragma unroll
    for (int i = 0; i < MT; ++i)
        #pragma unroll
        for (int j = 0; j < NT; ++j)
            #pragma unroll
            for (int q = 0; q < 4; ++q) acc[i][j][q] = 0.0f;

    auto loadA = [&](int kt, int buf) {
        const float* Ag = A + (long long)bm * lda + kt * BK;
        #pragma unroll
        for (int i = 0; i < 2; ++i) {
            const int id = t + i * 256;
            const int m = id >> 2, kc = id & 3;
            cp16(&As[buf][m * 20 + kc * 4], Ag + (long long)m * lda + kc * 4);
        }
    };
    auto loadB = [&](int kt, int buf) {
        if (TRANSB) {
            const float* Bg = B + (long long)bn * ldb + kt * BK;
            #pragma unroll
            for (int i = 0; i < (BN * 4) / 256; ++i) {
                const int id = t + i * 256;
                const int n = id >> 2, kc = id & 3;
                cp16(&Bs[buf][n * 20 + kc * 4], Bg + (long long)n * ldb + kc * 4);
            }
        } else {
            const float* Bg = B + (long long)(kt * BK) * ldb + bn;
            #pragma unroll
            for (int i = 0; i < (BK * (BN / 4)) / 256; ++i) {
                const int id = t + i * 256;
                const int k = id / (BN / 4), nc = id % (BN / 4);
                cp16(&Bs[buf][k * BNP + nc * 4], Bg + (long long)k * ldb + nc * 4);
            }
        }
    };

    const int nk = K / BK;
    loadA(0, 0); loadB(0, 0); cp_commit();

    for (int kt = 0; kt < nk; ++kt) {
        const int buf = kt & 1;
        if (kt + 1 < nk) {
            loadA(kt + 1, buf ^ 1); loadB(kt + 1, buf ^ 1); cp_commit();
            cp_wait1();
        } else {
            cp_wait0();
        }
        __syncthreads();

        #pragma unroll
        for (int ks = 0; ks < 2; ++ks) {
            const int k0 = ks * 8;
            uint32_t a[MT][4], b[NT][2];
            #pragma unroll
            for (int mt = 0; mt < MT; ++mt) {
                const int m = wmBase + mt * 16 + g;
                const float* p = &As[buf][m * 20 + k0 + tg];
                a[mt][0] = __float_as_uint(p[0]);
                a[mt][1] = __float_as_uint(p[8 * 20]);
                a[mt][2] = __float_as_uint(p[4]);
                a[mt][3] = __float_as_uint(p[8 * 20 + 4]);
            }
            #pragma unroll
            for (int nt = 0; nt < NT; ++nt) {
                const int n = wnBase + nt * 8 + g;
                if (TRANSB) {
                    const float* p = &Bs[buf][n * 20 + k0 + tg];
                    b[nt][0] = __float_as_uint(p[0]);
                    b[nt][1] = __float_as_uint(p[4]);
                } else {
                    const float* p = &Bs[buf][(k0 + tg) * BNP + n];
                    b[nt][0] = __float_as_uint(p[0]);
                    b[nt][1] = __float_as_uint(p[4 * BNP]);
                }
            }
            #pragma unroll
            for (int mt = 0; mt < MT; ++mt)
                #pragma unroll
                for (int nt = 0; nt < NT; ++nt)
                    mma_tf32(acc[mt][nt], a[mt], b[nt]);
        }
        __syncthreads();
    }

    #pragma unroll
    for (int mt = 0; mt < MT; ++mt) {
        #pragma unroll
        for (int nt = 0; nt < NT; ++nt) {
            const int r0 = bm + wmBase + mt * 16 + g;
            const int c0 = bn + wnBase + nt * 8 + tg * 2;
            #pragma unroll
            for (int half = 0; half < 2; ++half) {
                const int r = r0 + half * 8;
                float v0 = acc[mt][nt][half * 2 + 0];
                float v1 = acc[mt][nt][half * 2 + 1];
                if (EPI == 0) {
                    v0 *= alpha; v1 *= alpha;
                } else if (EPI == 1) {
                    v0 += bias[c0]     + res[(long long)r * ldr + c0];
                    v1 += bias[c0 + 1] + res[(long long)r * ldr + c0 + 1];
                } else {
                    const float z0 = v0 + bias[c0];
                    const float z1 = v1 + bias[c0 + 1];
                    v0 = 0.5f * z0 * (1.0f + erff(z0 * 0.70710678118654752440f));
                    v1 = 0.5f * z1 * (1.0f + erff(z1 * 0.70710678118654752440f));
                }
                if (CVT) { v0 = to_tf32(v0); v1 = to_tf32(v1); }
                float2 o; o.x = v0; o.y = v1;
                *(float2*)(C + (long long)r * ldc + c0) = o;
            }
        }
    }
}

// ---------------------------------------------------------------------------
// Launch sequence (graph-capturable: kernel launches only)
// ---------------------------------------------------------------------------
extern "C" void kernel_launch(void* const* d_in, const int* in_sizes, int n_in,
                              void* d_out, int out_size)
{
    const float* x     = (const float*)d_in[0];
    const float* y     = (const float*)d_in[1];
    const float* Wq    = (const float*)d_in[2];
    const float* Wk    = (const float*)d_in[3];
    const float* Wv    = (const float*)d_in[4];
    const float* li1_w = (const float*)d_in[5];
    const float* li1_b = (const float*)d_in[6];
    const float* ln1_w = (const float*)d_in[7];
    const float* ln1_b = (const float*)d_in[8];
    const float* ln2_w = (const float*)d_in[9];
    const float* ln2_b = (const float*)d_in[10];
    const float* ln3_w = (const float*)d_in[11];
    const float* ln3_b = (const float*)d_in[12];
    const float* li2_w = (const float*)d_in[13];
    const float* li2_b = (const float*)d_in[14];
    const float* li3_w = (const float*)d_in[15];
    const float* li3_b = (const float*)d_in[16];
    float* out = (float*)d_out;

    float *xn, *yn, *wqp, *wkp, *wvp, *w1, *w2, *w3;
    float *qb, *kb, *vb, *ob, *xo, *h1, *h2;
    cudaGetSymbolAddress((void**)&xn,  g_xn);
    cudaGetSymbolAddress((void**)&yn,  g_yn);
    cudaGetSymbolAddress((void**)&wqp, g_wqp);
    cudaGetSymbolAddress((void**)&wkp, g_wkp);
    cudaGetSymbolAddress((void**)&wvp, g_wvp);
    cudaGetSymbolAddress((void**)&w1,  g_w1);
    cudaGetSymbolAddress((void**)&w2,  g_w2);
    cudaGetSymbolAddress((void**)&w3,  g_w3);
    cudaGetSymbolAddress((void**)&qb,  g_q);
    cudaGetSymbolAddress((void**)&kb,  g_k);
    cudaGetSymbolAddress((void**)&vb,  g_v);
    cudaGetSymbolAddress((void**)&ob,  g_o);
    cudaGetSymbolAddress((void**)&xo,  g_xout);
    cudaGetSymbolAddress((void**)&h1,  g_h1);
    cudaGetSymbolAddress((void**)&h2,  g_h2);

    static int fa_attr_set = 0;
    if (!fa_attr_set) {
        cudaFuncSetAttribute(flash_attn_kernel,
                             cudaFuncAttributeMaxDynamicSharedMemorySize,
                             FA_SMEM_BYTES);
        fa_attr_set = 1;
    }

    // 1) LayerNorms of x and y (outputs tf32-rounded)
    ln_kernel<<<4096, 256>>>(x, ln1_w, ln1_b, xn);
    ln_kernel<<<4096, 256>>>(y, ln2_w, ln2_b, yn);

    // 2) Pack head weights to [C, H*D] (tf32) + round linear weights (tf32)
    pack_w_kernel<<<4096, 256>>>(Wq, Wk, Wv);
    round_tf32_kernel<<<1024, 256>>>(li1_w, w1, 1024 * 1024 / 4);
    round_tf32_kernel<<<4096, 256>>>(li2_w, w2, 1024 * 4096 / 4);
    round_tf32_kernel<<<4096, 256>>>(li3_w, w3, 4096 * 1024 / 4);

    // 3) Q/K/V projections: [4096,1024] @ [1024,1024]
    dim3 gProj(1024 / 128, 4096 / 128, 1);
    gemm_tc<128, 2, 4, false, 0, true><<<gProj, 256>>>(4096, 1024, 1024,
        xn, 1024, 0, 0,  wqp, 1024, 0, 0,  qb, 1024, 0, 0,
        1.0f, nullptr, nullptr, 0);
    gemm_tc<128, 2, 4, false, 0, true><<<gProj, 256>>>(4096, 1024, 1024,
        yn, 1024, 0, 0,  wkp, 1024, 0, 0,  kb, 1024, 0, 0,
        1.0f, nullptr, nullptr, 0);
    gemm_tc<128, 2, 4, false, 0, true><<<gProj, 256>>>(4096, 1024, 1024,
        yn, 1024, 0, 0,  wvp, 1024, 0, 0,  vb, 1024, 0, 0,
        1.0f, nullptr, nullptr, 0);

    // 4) Fused attention (scores + softmax + mask + PV), O tf32-rounded
    flash_attn_kernel<<<dim3(1, 16, 32), 256, FA_SMEM_BYTES>>>(qb, kb, vb, ob);

    // 5) x_out = x + O @ li1_w + li1_b (full fp32 output)
    gemm_tc<128, 2, 4, false, 1, false><<<gProj, 256>>>(4096, 1024, 1024,
        ob, 1024, 0, 0,  w1, 1024, 0, 0,  xo, 1024, 0, 0,
        1.0f, li1_b, x, 1024);

    // 6) h1 = LN(x_out) (tf32-rounded)
    ln_kernel<<<4096, 256>>>(xo, ln3_w, ln3_b, h1);

    // 7) h2 = gelu(h1 @ li2_w + li2_b)  [4096,1024]@[1024,4096] (tf32-rounded)
    dim3 gUp(4096 / 128, 4096 / 128, 1);
    gemm_tc<128, 2, 4, false, 2, true><<<gUp, 256>>>(4096, 4096, 1024,
        h1, 1024, 0, 0,  w2, 4096, 0, 0,  h2, 4096, 0, 0,
        1.0f, li2_b, nullptr, 0);

    // 8) out = x_out + h2 @ li3_w + li3_b  [4096,4096]@[4096,1024]
    dim3 gDn(1024 / 128, 4096 / 128, 1);
    gemm_tc<128, 2, 4, false, 1, false><<<gDn, 256>>>(4096, 1024, 4096,
        h2, 4096, 0, 0,  w3, 1024, 0, 0,  out, 1024, 0, 0,
        1.0f, li3_b, xo, 1024);
}

// round 6
// speedup vs baseline: 5.6323x; 1.6800x over previous
#include <cuda_runtime.h>
#include <cuda_fp16.h>
#include <math.h>
#include <stdint.h>

// ---------------------------------------------------------------------------
// Problem constants: B=2, S=2048, C1=C2=1024, H=16, D=64, W_EXP=4
//   rows = B*S = 4096
// ---------------------------------------------------------------------------

// ---------------- scratch (static __device__ — allocation-free) ------------
__device__ __half g_xn [4096 * 1024];
__device__ __half g_yn [4096 * 1024];
__device__ __half g_wqp[1024 * 1024];   // [H*D][C] transposed
__device__ __half g_wkp[1024 * 1024];
__device__ __half g_wvp[1024 * 1024];
__device__ __half g_w1t[1024 * 1024];   // [C1][H*D]   (N x K)
__device__ __half g_w2t[4096 * 1024];   // [4C1][C1]
__device__ __half g_w3t[1024 * 4096];   // [C1][4C1]
__device__ __half g_q  [4096 * 1024];   // pre-scaled by 0.125
__device__ __half g_k  [4096 * 1024];
__device__ __half g_v  [4096 * 1024];
__device__ __half g_o  [4096 * 1024];
__device__ __half g_h1 [4096 * 1024];
__device__ __half g_h2 [4096 * 4096];
__device__ float  g_xout[4096 * 1024];

// ---------------------------------------------------------------------------
// helpers
// ---------------------------------------------------------------------------
__device__ __forceinline__ void cp16(void* smem, const void* g) {
    uint32_t s = (uint32_t)__cvta_generic_to_shared(smem);
    asm volatile("cp.async.cg.shared.global [%0], [%1], 16;" :: "r"(s), "l"(g));
}
__device__ __forceinline__ void cp_commit() { asm volatile("cp.async.commit_group;"); }
__device__ __forceinline__ void cp_wait2()  { asm volatile("cp.async.wait_group 2;"); }
__device__ __forceinline__ void cp_wait1()  { asm volatile("cp.async.wait_group 1;"); }
__device__ __forceinline__ void cp_wait0()  { asm volatile("cp.async.wait_group 0;"); }

// m16n8k16 row.col f16 inputs, f32 accumulate
__device__ __forceinline__ void mma_f16(float* c, const uint32_t* a, const uint32_t* b) {
    asm volatile(
        "mma.sync.aligned.m16n8k16.row.col.f32.f16.f16.f32 "
        "{%0,%1,%2,%3}, {%4,%5,%6,%7}, {%8,%9}, {%0,%1,%2,%3};\n"
        : "+f"(c[0]), "+f"(c[1]), "+f"(c[2]), "+f"(c[3])
        : "r"(a[0]), "r"(a[1]), "r"(a[2]), "r"(a[3]), "r"(b[0]), "r"(b[1]));
}

__device__ __forceinline__ uint32_t f2h2(float lo, float hi) {
    __half2 h = __floats2half2_rn(lo, hi);
    return *(uint32_t*)&h;
}

// ---------------------------------------------------------------------------
// LayerNorm over last dim (C = 1024), fp16 output (feeds MMAs only).
// ---------------------------------------------------------------------------
__global__ void ln_kernel(const float* __restrict__ x,
                          const float* __restrict__ w,
                          const float* __restrict__ b,
                          __half* __restrict__ out)
{
    __shared__ float shs[8], shq[8];
    const int row = blockIdx.x;
    const float* xr = x + (long long)row * 1024;
    const int t = threadIdx.x;

    float4 f = *(const float4*)(xr + t * 4);
    float s = f.x + f.y + f.z + f.w;
    float q = f.x * f.x + f.y * f.y + f.z * f.z + f.w * f.w;
    #pragma unroll
    for (int o = 16; o; o >>= 1) {
        s += __shfl_xor_sync(0xFFFFFFFFu, s, o);
        q += __shfl_xor_sync(0xFFFFFFFFu, q, o);
    }
    const int wid = t >> 5, ln = t & 31;
    if (ln == 0) { shs[wid] = s; shq[wid] = q; }
    __syncthreads();
    if (wid == 0) {
        float a = (ln < 8) ? shs[ln] : 0.0f;
        float c = (ln < 8) ? shq[ln] : 0.0f;
        #pragma unroll
        for (int o = 4; o; o >>= 1) {
            a += __shfl_xor_sync(0xFFFFFFFFu, a, o);
            c += __shfl_xor_sync(0xFFFFFFFFu, c, o);
        }
        if (ln == 0) { shs[0] = a; shq[0] = c; }
    }
    __syncthreads();
    const float mu  = shs[0] * (1.0f / 1024.0f);
    const float var = shq[0] * (1.0f / 1024.0f) - mu * mu;
    const float rs  = rsqrtf(var + 1e-5f);

    float4 wv = *(const float4*)(w + t * 4);
    float4 bv = *(const float4*)(b + t * 4);
    uint2 o2;
    o2.x = f2h2((f.x - mu) * rs * wv.x + bv.x, (f.y - mu) * rs * wv.y + bv.y);
    o2.y = f2h2((f.z - mu) * rs * wv.z + bv.z, (f.w - mu) * rs * wv.w + bv.w);
    *(uint2*)(out + (long long)row * 1024 + t * 4) = o2;
}

// ---------------------------------------------------------------------------
// Tiled transpose + fp32->fp16: dst[n][k] = (half)src[k][n].
// grid: (N/32, K/32, batches), block (32, 8).
// ---------------------------------------------------------------------------
__global__ void transpose_f2h(const float* __restrict__ src, __half* __restrict__ dst,
                              int srcLd, int dstLd,
                              long long srcBatch, long long dstBatch)
{
    __shared__ float tile[32][33];
    const float* s = src + blockIdx.z * srcBatch;
    __half*      d = dst + blockIdx.z * dstBatch;
    const int n0 = blockIdx.x * 32, k0 = blockIdx.y * 32;
    const int tx = threadIdx.x, ty = threadIdx.y;
    #pragma unroll
    for (int j = 0; j < 32; j += 8)
        tile[ty + j][tx] = s[(long long)(k0 + ty + j) * srcLd + n0 + tx];
    __syncthreads();
    #pragma unroll
    for (int j = 0; j < 32; j += 8)
        d[(long long)(n0 + ty + j) * dstLd + k0 + tx] = __float2half_rn(tile[tx][ty + j]);
}

// ---------------------------------------------------------------------------
// fp16 tensor-core GEMM:  C[M][N] = epi(A[M][K] @ B[N][K]^T)
// BM=128, BN=128, BK=32 (halves). 8 warps (2x4): warp tile 64x32.
// m16n8k16 f16 mma, fp32 accum. cp.async double-buffered.
// smem: As/Bs [128][40] halves (pad 32->40, conflict-free).
// EPI: 0 = half out, alpha*acc
//      1 = float out, acc + bias[n] + res[m][n]
//      2 = half out, gelu(acc + bias[n])
// ---------------------------------------------------------------------------
template<int EPI>
__global__ __launch_bounds__(256, 2)
void gemm_h(int M, int N, int K,
            const __half* __restrict__ A, int lda,
            const __half* __restrict__ B, int ldb,
            void* __restrict__ Cout, int ldc,
            float alpha,
            const float* __restrict__ bias,
            const float* __restrict__ res, int ldr)
{
    __shared__ __half As[2][128 * 40];
    __shared__ __half Bs[2][128 * 40];

    const int bm = blockIdx.y * 128;
    const int bn = blockIdx.x * 128;
    const int t    = threadIdx.x;
    const int warp = t >> 5;
    const int lane = t & 31;
    const int g  = lane >> 2;
    const int tg = lane & 3;
    const int wmBase = (warp >> 2) * 64;   // 2 warps in M
    const int wnBase = (warp & 3) * 32;    // 4 warps in N

    float acc[4][4][4];
    #pragma unroll
    for (int i = 0; i < 4; ++i)
        #pragma unroll
        for (int j = 0; j < 4; ++j)
            #pragma unroll
            for (int q = 0; q < 4; ++q) acc[i][j][q] = 0.0f;

    auto loadA = [&](int kt, int buf) {
        const __half* Ag = A + (long long)bm * lda + kt * 32;
        #pragma unroll
        for (int i = 0; i < 2; ++i) {
            const int id = t + i * 256;          // 512 chunks of 16B
            const int m = id >> 2, c = id & 3;
            cp16(&As[buf][m * 40 + c * 8], Ag + (long long)m * lda + c * 8);
        }
    };
    auto loadB = [&](int kt, int buf) {
        const __half* Bg = B + (long long)bn * ldb + kt * 32;
        #pragma unroll
        for (int i = 0; i < 2; ++i) {
            const int id = t + i * 256;
            const int n = id >> 2, c = id & 3;
            cp16(&Bs[buf][n * 40 + c * 8], Bg + (long long)n * ldb + c * 8);
        }
    };

    const int nk = K >> 5;
    loadA(0, 0); loadB(0, 0); cp_commit();

    for (int kt = 0; kt < nk; ++kt) {
        const int buf = kt & 1;
        if (kt + 1 < nk) {
            loadA(kt + 1, buf ^ 1); loadB(kt + 1, buf ^ 1); cp_commit();
            cp_wait1();
        } else {
            cp_wait0();
        }
        __syncthreads();

        #pragma unroll
        for (int ks = 0; ks < 2; ++ks) {
            const int k0 = ks * 16;
            uint32_t a[4][4], b[4][2];
            #pragma unroll
            for (int mt = 0; mt < 4; ++mt) {
                const int m = wmBase + mt * 16 + g;
                const __half* p = &As[buf][m * 40 + k0 + 2 * tg];
                a[mt][0] = *(const uint32_t*)p;
                a[mt][1] = *(const uint32_t*)(p + 8 * 40);
                a[mt][2] = *(const uint32_t*)(p + 8);
                a[mt][3] = *(const uint32_t*)(p + 8 * 40 + 8);
            }
            #pragma unroll
            for (int nt = 0; nt < 4; ++nt) {
                const int n = wnBase + nt * 8 + g;
                const __half* p = &Bs[buf][n * 40 + k0 + 2 * tg];
                b[nt][0] = *(const uint32_t*)p;
                b[nt][1] = *(const uint32_t*)(p + 8);
            }
            #pragma unroll
            for (int mt = 0; mt < 4; ++mt)
                #pragma unroll
                for (int nt = 0; nt < 4; ++nt)
                    mma_f16(acc[mt][nt], a[mt], b[nt]);
        }
        __syncthreads();
    }

    // ---- epilogue ----
    #pragma unroll
    for (int mt = 0; mt < 4; ++mt) {
        #pragma unroll
        for (int nt = 0; nt < 4; ++nt) {
            const int r0 = bm + wmBase + mt * 16 + g;
            const int c0 = bn + wnBase + nt * 8 + 2 * tg;
            #pragma unroll
            for (int half = 0; half < 2; ++half) {
                const int r = r0 + half * 8;
                float v0 = acc[mt][nt][half * 2 + 0];
                float v1 = acc[mt][nt][half * 2 + 1];
                if (EPI == 0) {
                    v0 *= alpha; v1 *= alpha;
                    *(uint32_t*)((__half*)Cout + (long long)r * ldc + c0) = f2h2(v0, v1);
                } else if (EPI == 1) {
                    v0 += bias[c0]     + res[(long long)r * ldr + c0];
                    v1 += bias[c0 + 1] + res[(long long)r * ldr + c0 + 1];
                    float2 o; o.x = v0; o.y = v1;
                    *(float2*)((float*)Cout + (long long)r * ldc + c0) = o;
                } else {
                    const float z0 = v0 + bias[c0];
                    const float z1 = v1 + bias[c0 + 1];
                    v0 = 0.5f * z0 * (1.0f + erff(z0 * 0.70710678118654752440f));
                    v1 = 0.5f * z1 * (1.0f + erff(z1 * 0.70710678118654752440f));
                    *(uint32_t*)((__half*)Cout + (long long)r * ldc + c0) = f2h2(v0, v1);
                }
            }
        }
    }
}

// ---------------------------------------------------------------------------
// Fused flash attention, fp16 operands, post-softmax masking.
//   O_s = (1/sum_all_t exp(s_t - m)) * sum_{t>s} exp(s_t - m) v_t
// Per CTA: one (z, 128-row) block; 8 warps x 16 rows; t-tiles of 64.
// Q pre-scaled by 0.125 (proj epilogue). smem (dynamic, 55296 B):
//   sP [128][72] halves (Q staging + masked P), sK/sV [2][64][72] halves.
// V B-fragments built from dual u16 LDS (conflict-free).
// ---------------------------------------------------------------------------
#define FA_SMEM_BYTES ((128*72 + 2*64*72 + 2*64*72) * 2)   // 55296

__global__ __launch_bounds__(256)
void flash_attn_kernel(const __half* __restrict__ Qg,
                       const __half* __restrict__ Kg,
                       const __half* __restrict__ Vg,
                       __half* __restrict__ Og)
{
    extern __shared__ __half sm_h[];
    __half* sP = sm_h;                           // [128][72]
    __half* sK = sm_h + 128 * 72;                // [2][64*72]
    __half* sV = sm_h + 128 * 72 + 2 * 64 * 72;  // [2][64*72]

    const int z = blockIdx.z;
    const long long zb = z >> 4, zh = z & 15;
    const long long base = zb * (2048LL * 1024) + zh * 64;
    const __half* Qp = Qg + base;
    const __half* Kp = Kg + base;
    const __half* Vp = Vg + base;

    const int bm = blockIdx.y * 128;
    const int t = threadIdx.x;
    const int w = t >> 5, lane = t & 31, g = lane >> 2, tg = lane & 3;

    // ---- stage Q tile (128 x 64 halves) into sP ----
    {
        const __half* Qa = Qp + (long long)bm * 1024;
        #pragma unroll
        for (int i = 0; i < 4; ++i) {
            const int id = t + i * 256;          // 1024 chunks of 16B
            const int m = id >> 3, c = id & 7;
            cp16(&sP[m * 72 + c * 8], Qa + (long long)m * 1024 + c * 8);
        }
        cp_commit();
    }

    auto loadKV = [&](int it, int buf) {
        const __half* Ka = Kp + (long long)(it * 64) * 1024;
        const __half* Va = Vp + (long long)(it * 64) * 1024;
        #pragma unroll
        for (int i = 0; i < 2; ++i) {
            const int id = t + i * 256;          // 512 chunks
            const int r = id >> 3, c = id & 7;
            cp16(&sK[buf * (64 * 72) + r * 72 + c * 8], Ka + (long long)r * 1024 + c * 8);
        }
        #pragma unroll
        for (int i = 0; i < 2; ++i) {
            const int id = t + i * 256;
            const int r = id >> 3, c = id & 7;
            cp16(&sV[buf * (64 * 72) + r * 72 + c * 8], Va + (long long)r * 1024 + c * 8);
        }
        cp_commit();
    };
    loadKV(0, 0);
    loadKV(1, 1);

    cp_wait2();                 // Q group done
    __syncthreads();

    // ---- Q fragments (already scaled by 0.125) ----
    uint32_t aq[4][4];
    {
        const int m = w * 16 + g;
        #pragma unroll
        for (int kk = 0; kk < 4; ++kk) {
            const __half* p = &sP[m * 72 + kk * 16 + 2 * tg];
            aq[kk][0] = *(const uint32_t*)p;
            aq[kk][1] = *(const uint32_t*)(p + 8 * 72);
            aq[kk][2] = *(const uint32_t*)(p + 8);
            aq[kk][3] = *(const uint32_t*)(p + 8 * 72 + 8);
        }
    }
    // sP rows are warp-private; later P stores hit the same 16-row band only.

    float accO[8][4];
    #pragma unroll
    for (int i = 0; i < 8; ++i)
        #pragma unroll
        for (int j = 0; j < 4; ++j) accO[i][j] = 0.0f;
    float m0 = -1e30f, m1 = -1e30f, l0 = 0.0f, l1 = 0.0f;

    const int srow0 = bm + w * 16 + g;
    const int srow1 = srow0 + 8;

    for (int it = 0; it < 32; ++it) {
        const int buf = it & 1;
        if (it + 1 < 32) cp_wait1(); else cp_wait0();
        __syncthreads();

        // ---- S = Q K^T  (Q pre-scaled) ----
        float s[8][4];
        #pragma unroll
        for (int i = 0; i < 8; ++i) { s[i][0]=0; s[i][1]=0; s[i][2]=0; s[i][3]=0; }
        const __half* Kb = &sK[buf * (64 * 72)];
        #pragma unroll
        for (int kk = 0; kk < 4; ++kk) {
            const int k0 = kk * 16;
            #pragma unroll
            for (int nt = 0; nt < 8; ++nt) {
                uint32_t b[2];
                const __half* p = &Kb[(nt * 8 + g) * 72 + k0 + 2 * tg];
                b[0] = *(const uint32_t*)p;
                b[1] = *(const uint32_t*)(p + 8);
                mma_f16(s[nt], aq[kk], b);
            }
        }

        // ---- online softmax (l over ALL t; mask applies to P only) ----
        float tmax0 = s[0][0], tmax1 = s[0][2];
        #pragma unroll
        for (int nt = 0; nt < 8; ++nt) {
            tmax0 = fmaxf(tmax0, fmaxf(s[nt][0], s[nt][1]));
            tmax1 = fmaxf(tmax1, fmaxf(s[nt][2], s[nt][3]));
        }
        tmax0 = fmaxf(tmax0, __shfl_xor_sync(0xFFFFFFFFu, tmax0, 1));
        tmax0 = fmaxf(tmax0, __shfl_xor_sync(0xFFFFFFFFu, tmax0, 2));
        tmax1 = fmaxf(tmax1, __shfl_xor_sync(0xFFFFFFFFu, tmax1, 1));
        tmax1 = fmaxf(tmax1, __shfl_xor_sync(0xFFFFFFFFu, tmax1, 2));
        const float mn0 = fmaxf(m0, tmax0), mn1 = fmaxf(m1, tmax1);
        const float al0 = __expf(m0 - mn0), al1 = __expf(m1 - mn1);
        float ls0 = 0.0f, ls1 = 0.0f;
        #pragma unroll
        for (int nt = 0; nt < 8; ++nt) {
            s[nt][0] = __expf(s[nt][0] - mn0); ls0 += s[nt][0];
            s[nt][1] = __expf(s[nt][1] - mn0); ls0 += s[nt][1];
            s[nt][2] = __expf(s[nt][2] - mn1); ls1 += s[nt][2];
            s[nt][3] = __expf(s[nt][3] - mn1); ls1 += s[nt][3];
        }
        ls0 += __shfl_xor_sync(0xFFFFFFFFu, ls0, 1);
        ls0 += __shfl_xor_sync(0xFFFFFFFFu, ls0, 2);
        ls1 += __shfl_xor_sync(0xFFFFFFFFu, ls1, 1);
        ls1 += __shfl_xor_sync(0xFFFFFFFFu, ls1, 2);
        l0 = l0 * al0 + ls0;  l1 = l1 * al1 + ls1;
        m0 = mn0;  m1 = mn1;
        #pragma unroll
        for (int nt = 0; nt < 8; ++nt) {
            accO[nt][0] *= al0; accO[nt][1] *= al0;
            accO[nt][2] *= al1; accO[nt][3] *= al1;
        }

        // ---- masked fp16 P -> sP (warp-private rows) ----
        const int tbase = it * 64;
        #pragma unroll
        for (int nt = 0; nt < 8; ++nt) {
            const int tc = tbase + nt * 8 + 2 * tg;
            const float p0 = (tc     > srow0) ? s[nt][0] : 0.0f;
            const float p1 = (tc + 1 > srow0) ? s[nt][1] : 0.0f;
            const float p2 = (tc     > srow1) ? s[nt][2] : 0.0f;
            const float p3 = (tc + 1 > srow1) ? s[nt][3] : 0.0f;
            *(uint32_t*)&sP[(w * 16 + g)     * 72 + nt * 8 + 2 * tg] = f2h2(p0, p1);
            *(uint32_t*)&sP[(w * 16 + g + 8) * 72 + nt * 8 + 2 * tg] = f2h2(p2, p3);
        }
        __syncwarp();

        // ---- O += P V ----
        const __half* Vb = &sV[buf * (64 * 72)];
        #pragma unroll
        for (int kk = 0; kk < 4; ++kk) {
            const int k0 = kk * 16;
            uint32_t a[4];
            const __half* pa = &sP[(w * 16 + g) * 72 + k0 + 2 * tg];
            a[0] = *(const uint32_t*)pa;
            a[1] = *(const uint32_t*)(pa + 8 * 72);
            a[2] = *(const uint32_t*)(pa + 8);
            a[3] = *(const uint32_t*)(pa + 8 * 72 + 8);
            #pragma unroll
            for (int nt = 0; nt < 8; ++nt) {
                const int d = nt * 8 + g;
                const int t0 = k0 + 2 * tg;
                uint32_t b[2];
                {
                    const uint16_t x0 = *(const uint16_t*)&Vb[(t0)     * 72 + d];
                    const uint16_t x1 = *(const uint16_t*)&Vb[(t0 + 1) * 72 + d];
                    b[0] = (uint32_t)x0 | ((uint32_t)x1 << 16);
                    const uint16_t x2 = *(const uint16_t*)&Vb[(t0 + 8) * 72 + d];
                    const uint16_t x3 = *(const uint16_t*)&Vb[(t0 + 9) * 72 + d];
                    b[1] = (uint32_t)x2 | ((uint32_t)x3 << 16);
                }
                mma_f16(accO[nt], a, b);
            }
        }
        __syncthreads();
        if (it + 2 < 32) loadKV(it + 2, buf);
    }

    // ---- epilogue: O /= l, write fp16 concat-head layout ----
    const float inv0 = 1.0f / l0, inv1 = 1.0f / l1;
    __half* Ob = Og + zb * (2048LL * 1024) + zh * 64;
    #pragma unroll
    for (int nt = 0; nt < 8; ++nt) {
        const int c = nt * 8 + 2 * tg;
        *(uint32_t*)(Ob + (long long)srow0 * 1024 + c) =
            f2h2(accO[nt][0] * inv0, accO[nt][1] * inv0);
        *(uint32_t*)(Ob + (long long)srow1 * 1024 + c) =
            f2h2(accO[nt][2] * inv1, accO[nt][3] * inv1);
    }
}

// ---------------------------------------------------------------------------
// Launch sequence (graph-capturable: kernel launches only)
// ---------------------------------------------------------------------------
extern "C" void kernel_launch(void* const* d_in, const int* in_sizes, int n_in,
                              void* d_out, int out_size)
{
    const float* x     = (const float*)d_in[0];
    const float* y     = (const float*)d_in[1];
    const float* Wq    = (const float*)d_in[2];
    const float* Wk    = (const float*)d_in[3];
    const float* Wv    = (const float*)d_in[4];
    const float* li1_w = (const float*)d_in[5];
    const float* li1_b = (const float*)d_in[6];
    const float* ln1_w = (const float*)d_in[7];
    const float* ln1_b = (const float*)d_in[8];
    const float* ln2_w = (const float*)d_in[9];
    const float* ln2_b = (const float*)d_in[10];
    const float* ln3_w = (const float*)d_in[11];
    const float* ln3_b = (const float*)d_in[12];
    const float* li2_w = (const float*)d_in[13];
    const float* li2_b = (const float*)d_in[14];
    const float* li3_w = (const float*)d_in[15];
    const float* li3_b = (const float*)d_in[16];
    float* out = (float*)d_out;

    __half *xn, *yn, *wqp, *wkp, *wvp, *w1t, *w2t, *w3t;
    __half *qh, *kh, *vh, *oh, *h1, *h2;
    float *xo;
    cudaGetSymbolAddress((void**)&xn,  g_xn);
    cudaGetSymbolAddress((void**)&yn,  g_yn);
    cudaGetSymbolAddress((void**)&wqp, g_wqp);
    cudaGetSymbolAddress((void**)&wkp, g_wkp);
    cudaGetSymbolAddress((void**)&wvp, g_wvp);
    cudaGetSymbolAddress((void**)&w1t, g_w1t);
    cudaGetSymbolAddress((void**)&w2t, g_w2t);
    cudaGetSymbolAddress((void**)&w3t, g_w3t);
    cudaGetSymbolAddress((void**)&qh,  g_q);
    cudaGetSymbolAddress((void**)&kh,  g_k);
    cudaGetSymbolAddress((void**)&vh,  g_v);
    cudaGetSymbolAddress((void**)&oh,  g_o);
    cudaGetSymbolAddress((void**)&h1,  g_h1);
    cudaGetSymbolAddress((void**)&h2,  g_h2);
    cudaGetSymbolAddress((void**)&xo,  g_xout);

    static int fa_attr_set = 0;
    if (!fa_attr_set) {
        cudaFuncSetAttribute(flash_attn_kernel,
                             cudaFuncAttributeMaxDynamicSharedMemorySize,
                             FA_SMEM_BYTES);
        fa_attr_set = 1;
    }

    const dim3 tb(32, 8);

    // 1) LayerNorms of x and y (fp16 outputs)
    ln_kernel<<<4096, 256>>>(x, ln1_w, ln1_b, xn);
    ln_kernel<<<4096, 256>>>(y, ln2_w, ln2_b, yn);

    // 2) Transpose-pack all weights to [N][K] fp16
    //    Head weights [H][C][D]: per-head transpose -> [H*D][C]
    transpose_f2h<<<dim3(2, 32, 16), tb>>>(Wq, wqp, 64, 1024, 65536, 65536);
    transpose_f2h<<<dim3(2, 32, 16), tb>>>(Wk, wkp, 64, 1024, 65536, 65536);
    transpose_f2h<<<dim3(2, 32, 16), tb>>>(Wv, wvp, 64, 1024, 65536, 65536);
    transpose_f2h<<<dim3(32, 32, 1),  tb>>>(li1_w, w1t, 1024, 1024, 0, 0);
    transpose_f2h<<<dim3(128, 32, 1), tb>>>(li2_w, w2t, 4096, 1024, 0, 0);
    transpose_f2h<<<dim3(32, 128, 1), tb>>>(li3_w, w3t, 1024, 4096, 0, 0);

    // 3) Q/K/V projections (Q pre-scaled by D^-0.5 = 0.125, exact)
    dim3 gProj(1024 / 128, 4096 / 128, 1);
    gemm_h<0><<<gProj, 256>>>(4096, 1024, 1024, xn, 1024, wqp, 1024,
                              qh, 1024, 0.125f, nullptr, nullptr, 0);
    gemm_h<0><<<gProj, 256>>>(4096, 1024, 1024, yn, 1024, wkp, 1024,
                              kh, 1024, 1.0f, nullptr, nullptr, 0);
    gemm_h<0><<<gProj, 256>>>(4096, 1024, 1024, yn, 1024, wvp, 1024,
                              vh, 1024, 1.0f, nullptr, nullptr, 0);

    // 4) Fused attention (scores + softmax + post-mask + PV)
    flash_attn_kernel<<<dim3(1, 16, 32), 256, FA_SMEM_BYTES>>>(qh, kh, vh, oh);

    // 5) x_out = x + O @ li1_w + li1_b  (fp32 out)
    gemm_h<1><<<gProj, 256>>>(4096, 1024, 1024, oh, 1024, w1t, 1024,
                              xo, 1024, 1.0f, li1_b, x, 1024);

    // 6) h1 = LN(x_out) (fp16)
    ln_kernel<<<4096, 256>>>(xo, ln3_w, ln3_b, h1);

    // 7) h2 = gelu(h1 @ li2_w + li2_b)  (fp16)
    dim3 gUp(4096 / 128, 4096 / 128, 1);
    gemm_h<2><<<gUp, 256>>>(4096, 4096, 1024, h1, 1024, w2t, 1024,
                            h2, 4096, 1.0f, li2_b, nullptr, 0);

    // 8) out = x_out + h2 @ li3_w + li3_b  (fp32 out)
    dim3 gDn(1024 / 128, 4096 / 128, 1);
    gemm_h<1><<<gDn, 256>>>(4096, 1024, 4096, h2, 4096, w3t, 4096,
                            out, 1024, 1.0f, li3_b, xo, 1024);
}

// round 11
// speedup vs baseline: 5.8379x; 1.0365x over previous
#include <cuda_runtime.h>
#include <cuda_fp16.h>
#include <math.h>
#include <stdint.h>

// ---------------------------------------------------------------------------
// Problem constants: B=2, S=2048, C1=C2=1024, H=16, D=64, W_EXP=4
//   rows = B*S = 4096
// ---------------------------------------------------------------------------

// ---------------- scratch (static __device__ — allocation-free) ------------
__device__ __align__(16) __half g_xn [4096 * 1024];
__device__ __align__(16) __half g_yn [4096 * 1024];
__device__ __align__(16) __half g_wqp[1024 * 1024];   // [H*D][C]  (N x K)
__device__ __align__(16) __half g_wkp[1024 * 1024];
__device__ __align__(16) __half g_wvp[1024 * 1024];
__device__ __align__(16) __half g_w1t[1024 * 1024];   // [C1][H*D]
__device__ __align__(16) __half g_w2t[4096 * 1024];   // [4C1][C1]
__device__ __align__(16) __half g_w3t[1024 * 4096];   // [C1][4C1]
__device__ __align__(16) __half g_q  [4096 * 1024];   // pre-scaled by 0.125
__device__ __align__(16) __half g_k  [4096 * 1024];
__device__ __align__(16) __half g_v  [4096 * 1024];
__device__ __align__(16) __half g_o  [4096 * 1024];
__device__ __align__(16) __half g_h1 [4096 * 1024];
__device__ __align__(16) __half g_h2 [4096 * 4096];
__device__ __align__(16) float  g_xout[4096 * 1024];

// ---------------------------------------------------------------------------
// helpers
// ---------------------------------------------------------------------------
__device__ __forceinline__ void cp16(void* smem, const void* g) {
    uint32_t s = (uint32_t)__cvta_generic_to_shared(smem);
    asm volatile("cp.async.cg.shared.global [%0], [%1], 16;" :: "r"(s), "l"(g));
}
__device__ __forceinline__ void cp_commit() { asm volatile("cp.async.commit_group;"); }
__device__ __forceinline__ void cp_wait2()  { asm volatile("cp.async.wait_group 2;"); }
__device__ __forceinline__ void cp_wait1()  { asm volatile("cp.async.wait_group 1;"); }
__device__ __forceinline__ void cp_wait0()  { asm volatile("cp.async.wait_group 0;"); }

// m16n8k16 row.col f16 inputs, f32 accumulate
__device__ __forceinline__ void mma_f16(float* c, const uint32_t* a, const uint32_t* b) {
    asm volatile(
        "mma.sync.aligned.m16n8k16.row.col.f32.f16.f16.f32 "
        "{%0,%1,%2,%3}, {%4,%5,%6,%7}, {%8,%9}, {%0,%1,%2,%3};\n"
        : "+f"(c[0]), "+f"(c[1]), "+f"(c[2]), "+f"(c[3])
        : "r"(a[0]), "r"(a[1]), "r"(a[2]), "r"(a[3]), "r"(b[0]), "r"(b[1]));
}

// ldmatrix: 4x 8x8 b16 tiles. addr is a per-lane shared-space byte address.
__device__ __forceinline__ void ldsm4(uint32_t* r, uint32_t addr) {
    asm volatile("ldmatrix.sync.aligned.m8n8.x4.shared.b16 {%0,%1,%2,%3}, [%4];"
                 : "=r"(r[0]), "=r"(r[1]), "=r"(r[2]), "=r"(r[3]) : "r"(addr));
}
__device__ __forceinline__ void ldsm4t(uint32_t* r, uint32_t addr) {
    asm volatile("ldmatrix.sync.aligned.m8n8.x4.trans.shared.b16 {%0,%1,%2,%3}, [%4];"
                 : "=r"(r[0]), "=r"(r[1]), "=r"(r[2]), "=r"(r[3]) : "r"(addr));
}

__device__ __forceinline__ uint32_t f2h2(float lo, float hi) {
    __half2 h = __floats2half2_rn(lo, hi);
    return *(uint32_t*)&h;
}

// ---------------------------------------------------------------------------
// LayerNorm over last dim (C = 1024), fp16 output (feeds MMAs only).
// ---------------------------------------------------------------------------
__global__ void ln_kernel(const float* __restrict__ x,
                          const float* __restrict__ w,
                          const float* __restrict__ b,
                          __half* __restrict__ out)
{
    __shared__ float shs[8], shq[8];
    const int row = blockIdx.x;
    const float* xr = x + (long long)row * 1024;
    const int t = threadIdx.x;

    float4 f = *(const float4*)(xr + t * 4);
    float s = f.x + f.y + f.z + f.w;
    float q = f.x * f.x + f.y * f.y + f.z * f.z + f.w * f.w;
    #pragma unroll
    for (int o = 16; o; o >>= 1) {
        s += __shfl_xor_sync(0xFFFFFFFFu, s, o);
        q += __shfl_xor_sync(0xFFFFFFFFu, q, o);
    }
    const int wid = t >> 5, ln = t & 31;
    if (ln == 0) { shs[wid] = s; shq[wid] = q; }
    __syncthreads();
    if (wid == 0) {
        float a = (ln < 8) ? shs[ln] : 0.0f;
        float c = (ln < 8) ? shq[ln] : 0.0f;
        #pragma unroll
        for (int o = 4; o; o >>= 1) {
            a += __shfl_xor_sync(0xFFFFFFFFu, a, o);
            c += __shfl_xor_sync(0xFFFFFFFFu, c, o);
        }
        if (ln == 0) { shs[0] = a; shq[0] = c; }
    }
    __syncthreads();
    const float mu  = shs[0] * (1.0f / 1024.0f);
    const float var = shq[0] * (1.0f / 1024.0f) - mu * mu;
    const float rs  = rsqrtf(var + 1e-5f);

    float4 wv = *(const float4*)(w + t * 4);
    float4 bv = *(const float4*)(b + t * 4);
    uint2 o2;
    o2.x = f2h2((f.x - mu) * rs * wv.x + bv.x, (f.y - mu) * rs * wv.y + bv.y);
    o2.y = f2h2((f.z - mu) * rs * wv.z + bv.z, (f.w - mu) * rs * wv.w + bv.w);
    *(uint2*)(out + (long long)row * 1024 + t * 4) = o2;
}

// ---------------------------------------------------------------------------
// Tiled transpose + fp32->fp16: dst[n][k] = (half)src[k][n].
// ---------------------------------------------------------------------------
__global__ void transpose_f2h(const float* __restrict__ src, __half* __restrict__ dst,
                              int srcLd, int dstLd,
                              long long srcBatch, long long dstBatch)
{
    __shared__ float tile[32][33];
    const float* s = src + blockIdx.z * srcBatch;
    __half*      d = dst + blockIdx.z * dstBatch;
    const int n0 = blockIdx.x * 32, k0 = blockIdx.y * 32;
    const int tx = threadIdx.x, ty = threadIdx.y;
    #pragma unroll
    for (int j = 0; j < 32; j += 8)
        tile[ty + j][tx] = s[(long long)(k0 + ty + j) * srcLd + n0 + tx];
    __syncthreads();
    #pragma unroll
    for (int j = 0; j < 32; j += 8)
        d[(long long)(n0 + ty + j) * dstLd + k0 + tx] = __float2half_rn(tile[tx][ty + j]);
}

// ---------------------------------------------------------------------------
// fp16 tensor-core GEMM:  C[M][N] = epi(A[M][K] @ B[N][K]^T)
// BM=128, BN=128, BK=32 (halves). 8 warps (2x4): warp tile 64x32.
// m16n8k16 f16 mma, fp32 accum. cp.async double-buffered. ldmatrix loads.
// smem: As/Bs [128][40] halves (pad 32->40; 80B row stride conflict-free
// for the ldmatrix 8-row phase: bank quads 0,20,8,28,16,4,24,12).
// EPI: 0 = half out, alpha*acc
//      1 = float out, acc + bias[n] + res[m][n]
//      2 = half out, gelu(acc + bias[n])
// ---------------------------------------------------------------------------
template<int EPI>
__global__ __launch_bounds__(256, 2)
void gemm_h(int M, int N, int K,
            const __half* __restrict__ A, int lda,
            const __half* __restrict__ B, int ldb,
            void* __restrict__ Cout, int ldc,
            float alpha,
            const float* __restrict__ bias,
            const float* __restrict__ res, int ldr)
{
    __shared__ __half As[2][128 * 40];
    __shared__ __half Bs[2][128 * 40];

    const int bm = blockIdx.y * 128;
    const int bn = blockIdx.x * 128;
    const int t    = threadIdx.x;
    const int warp = t >> 5;
    const int lane = t & 31;
    const int g  = lane >> 2;
    const int tg = lane & 3;
    const int wmBase = (warp >> 2) * 64;   // 2 warps in M
    const int wnBase = (warp & 3) * 32;    // 4 warps in N

    // ldmatrix per-lane offset (bytes): group sub = lane>>3, row rr = lane&7.
    // row_off = rr + (sub&1)*8 ; col_off(halves) = (sub>>1)*8 ; stride 40 halves.
    const int sub = lane >> 3, rr = lane & 7;
    const uint32_t ldoff40 = (uint32_t)(((rr + (sub & 1) * 8) * 40 + (sub >> 1) * 8) * 2);
    const uint32_t asb = (uint32_t)__cvta_generic_to_shared(&As[0][0]);
    const uint32_t bsb = (uint32_t)__cvta_generic_to_shared(&Bs[0][0]);

    float acc[4][4][4];
    #pragma unroll
    for (int i = 0; i < 4; ++i)
        #pragma unroll
        for (int j = 0; j < 4; ++j)
            #pragma unroll
            for (int q = 0; q < 4; ++q) acc[i][j][q] = 0.0f;

    auto loadA = [&](int kt, int buf) {
        const __half* Ag = A + (long long)bm * lda + kt * 32;
        #pragma unroll
        for (int i = 0; i < 2; ++i) {
            const int id = t + i * 256;          // 512 chunks of 16B
            const int m = id >> 2, c = id & 3;
            cp16(&As[buf][m * 40 + c * 8], Ag + (long long)m * lda + c * 8);
        }
    };
    auto loadB = [&](int kt, int buf) {
        const __half* Bg = B + (long long)bn * ldb + kt * 32;
        #pragma unroll
        for (int i = 0; i < 2; ++i) {
            const int id = t + i * 256;
            const int n = id >> 2, c = id & 3;
            cp16(&Bs[buf][n * 40 + c * 8], Bg + (long long)n * ldb + c * 8);
        }
    };

    const int nk = K >> 5;
    loadA(0, 0); loadB(0, 0); cp_commit();

    for (int kt = 0; kt < nk; ++kt) {
        const int buf = kt & 1;
        if (kt + 1 < nk) {
            loadA(kt + 1, buf ^ 1); loadB(kt + 1, buf ^ 1); cp_commit();
            cp_wait1();
        } else {
            cp_wait0();
        }
        __syncthreads();

        const uint32_t aBuf = asb + (uint32_t)(buf * 128 * 40 * 2);
        const uint32_t bBuf = bsb + (uint32_t)(buf * 128 * 40 * 2);
        #pragma unroll
        for (int ks = 0; ks < 2; ++ks) {
            const int k0 = ks * 16;
            uint32_t a[4][4], b[4][2];
            #pragma unroll
            for (int mt = 0; mt < 4; ++mt)
                ldsm4(a[mt], aBuf + (uint32_t)(((wmBase + mt * 16) * 40 + k0) * 2) + ldoff40);
            #pragma unroll
            for (int p = 0; p < 2; ++p) {
                uint32_t rb[4];
                ldsm4(rb, bBuf + (uint32_t)(((wnBase + p * 16) * 40 + k0) * 2) + ldoff40);
                b[2 * p][0]     = rb[0]; b[2 * p][1]     = rb[2];
                b[2 * p + 1][0] = rb[1]; b[2 * p + 1][1] = rb[3];
            }
            #pragma unroll
            for (int mt = 0; mt < 4; ++mt)
                #pragma unroll
                for (int nt = 0; nt < 4; ++nt)
                    mma_f16(acc[mt][nt], a[mt], b[nt]);
        }
        __syncthreads();
    }

    // ---- epilogue ----
    #pragma unroll
    for (int mt = 0; mt < 4; ++mt) {
        #pragma unroll
        for (int nt = 0; nt < 4; ++nt) {
            const int r0 = bm + wmBase + mt * 16 + g;
            const int c0 = bn + wnBase + nt * 8 + 2 * tg;
            #pragma unroll
            for (int half = 0; half < 2; ++half) {
                const int r = r0 + half * 8;
                float v0 = acc[mt][nt][half * 2 + 0];
                float v1 = acc[mt][nt][half * 2 + 1];
                if (EPI == 0) {
                    v0 *= alpha; v1 *= alpha;
                    *(uint32_t*)((__half*)Cout + (long long)r * ldc + c0) = f2h2(v0, v1);
                } else if (EPI == 1) {
                    v0 += bias[c0]     + res[(long long)r * ldr + c0];
                    v1 += bias[c0 + 1] + res[(long long)r * ldr + c0 + 1];
                    float2 o; o.x = v0; o.y = v1;
                    *(float2*)((float*)Cout + (long long)r * ldc + c0) = o;
                } else {
                    const float z0 = v0 + bias[c0];
                    const float z1 = v1 + bias[c0 + 1];
                    v0 = 0.5f * z0 * (1.0f + erff(z0 * 0.70710678118654752440f));
                    v1 = 0.5f * z1 * (1.0f + erff(z1 * 0.70710678118654752440f));
                    *(uint32_t*)((__half*)Cout + (long long)r * ldc + c0) = f2h2(v0, v1);
                }
            }
        }
    }
}

// ---------------------------------------------------------------------------
// Fused flash attention, fp16 operands, post-softmax masking.
//   O_s = (1/sum_all_t exp(s_t - m)) * sum_{t>s} exp(s_t - m) v_t
// Per CTA: one (z, 128-row) block; 8 warps x 16 rows; t-tiles of 64.
// Q pre-scaled by 0.125 (proj epilogue). smem (dynamic, 55296 B):
//   sP [128][72] halves (Q staging + masked P), sK/sV [2][64][72] halves.
// All fragments via ldmatrix (V via .trans). 144B row stride conflict-free.
// ---------------------------------------------------------------------------
#define FA_SMEM_BYTES ((128*72 + 2*64*72 + 2*64*72) * 2)   // 55296

__global__ __launch_bounds__(256)
void flash_attn_kernel(const __half* __restrict__ Qg,
                       const __half* __restrict__ Kg,
                       const __half* __restrict__ Vg,
                       __half* __restrict__ Og)
{
    extern __shared__ __half sm_h[];
    __half* sP = sm_h;                           // [128][72]
    __half* sK = sm_h + 128 * 72;                // [2][64*72]
    __half* sV = sm_h + 128 * 72 + 2 * 64 * 72;  // [2][64*72]

    const int z = blockIdx.z;
    const long long zb = z >> 4, zh = z & 15;
    const long long base = zb * (2048LL * 1024) + zh * 64;
    const __half* Qp = Qg + base;
    const __half* Kp = Kg + base;
    const __half* Vp = Vg + base;

    const int bm = blockIdx.y * 128;
    const int t = threadIdx.x;
    const int w = t >> 5, lane = t & 31, g = lane >> 2, tg = lane & 3;

    // ldmatrix per-lane offset for stride-72 tiles
    const int sub = lane >> 3, rr = lane & 7;
    const uint32_t ldoff72 = (uint32_t)(((rr + (sub & 1) * 8) * 72 + (sub >> 1) * 8) * 2);
    const uint32_t sPb = (uint32_t)__cvta_generic_to_shared(sP);
    const uint32_t sKb = (uint32_t)__cvta_generic_to_shared(sK);
    const uint32_t sVb = (uint32_t)__cvta_generic_to_shared(sV);

    // ---- stage Q tile (128 x 64 halves) into sP ----
    {
        const __half* Qa = Qp + (long long)bm * 1024;
        #pragma unroll
        for (int i = 0; i < 4; ++i) {
            const int id = t + i * 256;          // 1024 chunks of 16B
            const int m = id >> 3, c = id & 7;
            cp16(&sP[m * 72 + c * 8], Qa + (long long)m * 1024 + c * 8);
        }
        cp_commit();
    }

    auto loadKV = [&](int it, int buf) {
        const __half* Ka = Kp + (long long)(it * 64) * 1024;
        const __half* Va = Vp + (long long)(it * 64) * 1024;
        #pragma unroll
        for (int i = 0; i < 2; ++i) {
            const int id = t + i * 256;          // 512 chunks
            const int r = id >> 3, c = id & 7;
            cp16(&sK[buf * (64 * 72) + r * 72 + c * 8], Ka + (long long)r * 1024 + c * 8);
        }
        #pragma unroll
        for (int i = 0; i < 2; ++i) {
            const int id = t + i * 256;
            const int r = id >> 3, c = id & 7;
            cp16(&sV[buf * (64 * 72) + r * 72 + c * 8], Va + (long long)r * 1024 + c * 8);
        }
        cp_commit();
    };
    loadKV(0, 0);
    loadKV(1, 1);

    cp_wait2();                 // Q group done
    __syncthreads();

    // ---- Q fragments (already scaled by 0.125) via ldmatrix ----
    uint32_t aq[4][4];
    #pragma unroll
    for (int kk = 0; kk < 4; ++kk)
        ldsm4(aq[kk], sPb + (uint32_t)(((w * 16) * 72 + kk * 16) * 2) + ldoff72);
    // sP rows are warp-private; later P stores hit the same 16-row band only.

    float accO[8][4];
    #pragma unroll
    for (int i = 0; i < 8; ++i)
        #pragma unroll
        for (int j = 0; j < 4; ++j) accO[i][j] = 0.0f;
    float m0 = -1e30f, m1 = -1e30f, l0 = 0.0f, l1 = 0.0f;

    const int srow0 = bm + w * 16 + g;
    const int srow1 = srow0 + 8;

    for (int it = 0; it < 32; ++it) {
        const int buf = it & 1;
        if (it + 1 < 32) cp_wait1(); else cp_wait0();
        __syncthreads();

        // ---- S = Q K^T ----
        float s[8][4];
        #pragma unroll
        for (int i = 0; i < 8; ++i) { s[i][0]=0; s[i][1]=0; s[i][2]=0; s[i][3]=0; }
        const uint32_t kBuf = sKb + (uint32_t)(buf * 64 * 72 * 2);
        #pragma unroll
        for (int kk = 0; kk < 4; ++kk) {
            const int k0 = kk * 16;
            uint32_t bfr[8][2];
            #pragma unroll
            for (int p = 0; p < 4; ++p) {
                uint32_t rb[4];
                ldsm4(rb, kBuf + (uint32_t)(((p * 16) * 72 + k0) * 2) + ldoff72);
                bfr[2 * p][0]     = rb[0]; bfr[2 * p][1]     = rb[2];
                bfr[2 * p + 1][0] = rb[1]; bfr[2 * p + 1][1] = rb[3];
            }
            #pragma unroll
            for (int nt = 0; nt < 8; ++nt)
                mma_f16(s[nt], aq[kk], bfr[nt]);
        }

        // ---- online softmax (l over ALL t; mask applies to P only) ----
        float tmax0 = s[0][0], tmax1 = s[0][2];
        #pragma unroll
        for (int nt = 0; nt < 8; ++nt) {
            tmax0 = fmaxf(tmax0, fmaxf(s[nt][0], s[nt][1]));
            tmax1 = fmaxf(tmax1, fmaxf(s[nt][2], s[nt][3]));
        }
        tmax0 = fmaxf(tmax0, __shfl_xor_sync(0xFFFFFFFFu, tmax0, 1));
        tmax0 = fmaxf(tmax0, __shfl_xor_sync(0xFFFFFFFFu, tmax0, 2));
        tmax1 = fmaxf(tmax1, __shfl_xor_sync(0xFFFFFFFFu, tmax1, 1));
        tmax1 = fmaxf(tmax1, __shfl_xor_sync(0xFFFFFFFFu, tmax1, 2));
        const float mn0 = fmaxf(m0, tmax0), mn1 = fmaxf(m1, tmax1);
        const float al0 = __expf(m0 - mn0), al1 = __expf(m1 - mn1);
        float ls0 = 0.0f, ls1 = 0.0f;
        #pragma unroll
        for (int nt = 0; nt < 8; ++nt) {
            s[nt][0] = __expf(s[nt][0] - mn0); ls0 += s[nt][0];
            s[nt][1] = __expf(s[nt][1] - mn0); ls0 += s[nt][1];
            s[nt][2] = __expf(s[nt][2] - mn1); ls1 += s[nt][2];
            s[nt][3] = __expf(s[nt][3] - mn1); ls1 += s[nt][3];
        }
        ls0 += __shfl_xor_sync(0xFFFFFFFFu, ls0, 1);
        ls0 += __shfl_xor_sync(0xFFFFFFFFu, ls0, 2);
        ls1 += __shfl_xor_sync(0xFFFFFFFFu, ls1, 1);
        ls1 += __shfl_xor_sync(0xFFFFFFFFu, ls1, 2);
        l0 = l0 * al0 + ls0;  l1 = l1 * al1 + ls1;
        m0 = mn0;  m1 = mn1;
        #pragma unroll
        for (int nt = 0; nt < 8; ++nt) {
            accO[nt][0] *= al0; accO[nt][1] *= al0;
            accO[nt][2] *= al1; accO[nt][3] *= al1;
        }

        // ---- masked fp16 P -> sP (warp-private rows) ----
        const int tbase = it * 64;
        #pragma unroll
        for (int nt = 0; nt < 8; ++nt) {
            const int tc = tbase + nt * 8 + 2 * tg;
            const float p0 = (tc     > srow0) ? s[nt][0] : 0.0f;
            const float p1 = (tc + 1 > srow0) ? s[nt][1] : 0.0f;
            const float p2 = (tc     > srow1) ? s[nt][2] : 0.0f;
            const float p3 = (tc + 1 > srow1) ? s[nt][3] : 0.0f;
            *(uint32_t*)&sP[(w * 16 + g)     * 72 + nt * 8 + 2 * tg] = f2h2(p0, p1);
            *(uint32_t*)&sP[(w * 16 + g + 8) * 72 + nt * 8 + 2 * tg] = f2h2(p2, p3);
        }
        __syncwarp();

        // ---- O += P V  (P via ldmatrix, V via ldmatrix.trans) ----
        const uint32_t vBuf = sVb + (uint32_t)(buf * 64 * 72 * 2);
        #pragma unroll
        for (int kk = 0; kk < 4; ++kk) {
            const int k0 = kk * 16;
            uint32_t a[4];
            ldsm4(a, sPb + (uint32_t)(((w * 16) * 72 + k0) * 2) + ldoff72);
            #pragma unroll
            for (int p = 0; p < 4; ++p) {
                uint32_t rb[4];
                ldsm4t(rb, vBuf + (uint32_t)((k0 * 72 + p * 16) * 2) + ldoff72);
                uint32_t blo[2] = { rb[0], rb[1] };
                uint32_t bhi[2] = { rb[2], rb[3] };
                mma_f16(accO[2 * p],     a, blo);
                mma_f16(accO[2 * p + 1], a, bhi);
            }
        }
        __syncthreads();
        if (it + 2 < 32) loadKV(it + 2, buf);
    }

    // ---- epilogue: O /= l, write fp16 concat-head layout ----
    const float inv0 = 1.0f / l0, inv1 = 1.0f / l1;
    __half* Ob = Og + zb * (2048LL * 1024) + zh * 64;
    #pragma unroll
    for (int nt = 0; nt < 8; ++nt) {
        const int c = nt * 8 + 2 * tg;
        *(uint32_t*)(Ob + (long long)srow0 * 1024 + c) =
            f2h2(accO[nt][0] * inv0, accO[nt][1] * inv0);
        *(uint32_t*)(Ob + (long long)srow1 * 1024 + c) =
            f2h2(accO[nt][2] * inv1, accO[nt][3] * inv1);
    }
}

// ---------------------------------------------------------------------------
// Launch sequence (graph-capturable: kernel launches only)
// ---------------------------------------------------------------------------
extern "C" void kernel_launch(void* const* d_in, const int* in_sizes, int n_in,
                              void* d_out, int out_size)
{
    const float* x     = (const float*)d_in[0];
    const float* y     = (const float*)d_in[1];
    const float* Wq    = (const float*)d_in[2];
    const float* Wk    = (const float*)d_in[3];
    const float* Wv    = (const float*)d_in[4];
    const float* li1_w = (const float*)d_in[5];
    const float* li1_b = (const float*)d_in[6];
    const float* ln1_w = (const float*)d_in[7];
    const float* ln1_b = (const float*)d_in[8];
    const float* ln2_w = (const float*)d_in[9];
    const float* ln2_b = (const float*)d_in[10];
    const float* ln3_w = (const float*)d_in[11];
    const float* ln3_b = (const float*)d_in[12];
    const float* li2_w = (const float*)d_in[13];
    const float* li2_b = (const float*)d_in[14];
    const float* li3_w = (const float*)d_in[15];
    const float* li3_b = (const float*)d_in[16];
    float* out = (float*)d_out;

    __half *xn, *yn, *wqp, *wkp, *wvp, *w1t, *w2t, *w3t;
    __half *qh, *kh, *vh, *oh, *h1, *h2;
    float *xo;
    cudaGetSymbolAddress((void**)&xn,  g_xn);
    cudaGetSymbolAddress((void**)&yn,  g_yn);
    cudaGetSymbolAddress((void**)&wqp, g_wqp);
    cudaGetSymbolAddress((void**)&wkp, g_wkp);
    cudaGetSymbolAddress((void**)&wvp, g_wvp);
    cudaGetSymbolAddress((void**)&w1t, g_w1t);
    cudaGetSymbolAddress((void**)&w2t, g_w2t);
    cudaGetSymbolAddress((void**)&w3t, g_w3t);
    cudaGetSymbolAddress((void**)&qh,  g_q);
    cudaGetSymbolAddress((void**)&kh,  g_k);
    cudaGetSymbolAddress((void**)&vh,  g_v);
    cudaGetSymbolAddress((void**)&oh,  g_o);
    cudaGetSymbolAddress((void**)&h1,  g_h1);
    cudaGetSymbolAddress((void**)&h2,  g_h2);
    cudaGetSymbolAddress((void**)&xo,  g_xout);

    static int fa_attr_set = 0;
    if (!fa_attr_set) {
        cudaFuncSetAttribute(flash_attn_kernel,
                             cudaFuncAttributeMaxDynamicSharedMemorySize,
                             FA_SMEM_BYTES);
        fa_attr_set = 1;
    }

    const dim3 tb(32, 8);

    // 1) LayerNorms of x and y (fp16 outputs)
    ln_kernel<<<4096, 256>>>(x, ln1_w, ln1_b, xn);
    ln_kernel<<<4096, 256>>>(y, ln2_w, ln2_b, yn);

    // 2) Transpose-pack all weights to [N][K] fp16
    transpose_f2h<<<dim3(2, 32, 16), tb>>>(Wq, wqp, 64, 1024, 65536, 65536);
    transpose_f2h<<<dim3(2, 32, 16), tb>>>(Wk, wkp, 64, 1024, 65536, 65536);
    transpose_f2h<<<dim3(2, 32, 16), tb>>>(Wv, wvp, 64, 1024, 65536, 65536);
    transpose_f2h<<<dim3(32, 32, 1),  tb>>>(li1_w, w1t, 1024, 1024, 0, 0);
    transpose_f2h<<<dim3(128, 32, 1), tb>>>(li2_w, w2t, 4096, 1024, 0, 0);
    transpose_f2h<<<dim3(32, 128, 1), tb>>>(li3_w, w3t, 1024, 4096, 0, 0);

    // 3) Q/K/V projections (Q pre-scaled by D^-0.5 = 0.125, exact)
    dim3 gProj(1024 / 128, 4096 / 128, 1);
    gemm_h<0><<<gProj, 256>>>(4096, 1024, 1024, xn, 1024, wqp, 1024,
                              qh, 1024, 0.125f, nullptr, nullptr, 0);
    gemm_h<0><<<gProj, 256>>>(4096, 1024, 1024, yn, 1024, wkp, 1024,
                              kh, 1024, 1.0f, nullptr, nullptr, 0);
    gemm_h<0><<<gProj, 256>>>(4096, 1024, 1024, yn, 1024, wvp, 1024,
                              vh, 1024, 1.0f, nullptr, nullptr, 0);

    // 4) Fused attention (scores + softmax + post-mask + PV)
    flash_attn_kernel<<<dim3(1, 16, 32), 256, FA_SMEM_BYTES>>>(qh, kh, vh, oh);

    // 5) x_out = x + O @ li1_w + li1_b  (fp32 out)
    gemm_h<1><<<gProj, 256>>>(4096, 1024, 1024, oh, 1024, w1t, 1024,
                              xo, 1024, 1.0f, li1_b, x, 1024);

    // 6) h1 = LN(x_out) (fp16)
    ln_kernel<<<4096, 256>>>(xo, ln3_w, ln3_b, h1);

    // 7) h2 = gelu(h1 @ li2_w + li2_b)  (fp16)
    dim3 gUp(4096 / 128, 4096 / 128, 1);
    gemm_h<2><<<gUp, 256>>>(4096, 4096, 1024, h1, 1024, w2t, 1024,
                            h2, 4096, 1.0f, li2_b, nullptr, 0);

    // 8) out = x_out + h2 @ li3_w + li3_b  (fp32 out)
    dim3 gDn(1024 / 128, 4096 / 128, 1);
    gemm_h<1><<<gDn, 256>>>(4096, 1024, 4096, h2, 4096, w3t, 4096,
                            out, 1024, 1.0f, li3_b, xo, 1024);
}

// round 12
// speedup vs baseline: 6.3488x; 1.0875x over previous
#include <cuda_runtime.h>
#include <cuda_fp16.h>
#include <math.h>
#include <stdint.h>

// ---------------------------------------------------------------------------
// Problem constants: B=2, S=2048, C1=C2=1024, H=16, D=64, W_EXP=4
//   rows = B*S = 4096
// ---------------------------------------------------------------------------

// ---------------- scratch (static __device__ — allocation-free) ------------
__device__ __align__(16) __half g_xn [4096 * 1024];
__device__ __align__(16) __half g_yn [4096 * 1024];
__device__ __align__(16) __half g_wqp[1024 * 1024];   // [H*D][C]  (N x K)
__device__ __align__(16) __half g_wkp[1024 * 1024];
__device__ __align__(16) __half g_wvp[1024 * 1024];
__device__ __align__(16) __half g_w1t[1024 * 1024];   // [C1][H*D]
__device__ __align__(16) __half g_w2t[4096 * 1024];   // [4C1][C1]
__device__ __align__(16) __half g_w3t[1024 * 4096];   // [C1][4C1]
__device__ __align__(16) __half g_q  [4096 * 1024];   // pre-scaled by 0.125
__device__ __align__(16) __half g_k  [4096 * 1024];
__device__ __align__(16) __half g_v  [4096 * 1024];
__device__ __align__(16) __half g_o  [4096 * 1024];
__device__ __align__(16) __half g_h1 [4096 * 1024];
__device__ __align__(16) __half g_h2 [4096 * 4096];
__device__ __align__(16) float  g_xout[4096 * 1024];

// ---------------------------------------------------------------------------
// helpers
// ---------------------------------------------------------------------------
__device__ __forceinline__ void cp16(void* smem, const void* g) {
    uint32_t s = (uint32_t)__cvta_generic_to_shared(smem);
    asm volatile("cp.async.cg.shared.global [%0], [%1], 16;" :: "r"(s), "l"(g));
}
__device__ __forceinline__ void cp_commit() { asm volatile("cp.async.commit_group;"); }
__device__ __forceinline__ void cp_wait2()  { asm volatile("cp.async.wait_group 2;"); }
__device__ __forceinline__ void cp_wait1()  { asm volatile("cp.async.wait_group 1;"); }
__device__ __forceinline__ void cp_wait0()  { asm volatile("cp.async.wait_group 0;"); }

// m16n8k16 row.col f16 inputs, f32 accumulate
__device__ __forceinline__ void mma_f16(float* c, const uint32_t* a, const uint32_t* b) {
    asm volatile(
        "mma.sync.aligned.m16n8k16.row.col.f32.f16.f16.f32 "
        "{%0,%1,%2,%3}, {%4,%5,%6,%7}, {%8,%9}, {%0,%1,%2,%3};\n"
        : "+f"(c[0]), "+f"(c[1]), "+f"(c[2]), "+f"(c[3])
        : "r"(a[0]), "r"(a[1]), "r"(a[2]), "r"(a[3]), "r"(b[0]), "r"(b[1]));
}

// ldmatrix: 4x 8x8 b16 tiles. addr is a per-lane shared-space byte address.
__device__ __forceinline__ void ldsm4(uint32_t* r, uint32_t addr) {
    asm volatile("ldmatrix.sync.aligned.m8n8.x4.shared.b16 {%0,%1,%2,%3}, [%4];"
                 : "=r"(r[0]), "=r"(r[1]), "=r"(r[2]), "=r"(r[3]) : "r"(addr));
}
__device__ __forceinline__ void ldsm4t(uint32_t* r, uint32_t addr) {
    asm volatile("ldmatrix.sync.aligned.m8n8.x4.trans.shared.b16 {%0,%1,%2,%3}, [%4];"
                 : "=r"(r[0]), "=r"(r[1]), "=r"(r[2]), "=r"(r[3]) : "r"(addr));
}

__device__ __forceinline__ uint32_t f2h2(float lo, float hi) {
    __half2 h = __floats2half2_rn(lo, hi);
    return *(uint32_t*)&h;
}

// ---------------------------------------------------------------------------
// Dual LayerNorm: rows 0..4095 -> LN(x; ln1), rows 4096..8191 -> LN(y; ln2).
// fp16 output (feeds MMAs only).
// ---------------------------------------------------------------------------
__global__ void ln2_kernel(const float* __restrict__ x, const float* __restrict__ y,
                           const float* __restrict__ w1, const float* __restrict__ b1,
                           const float* __restrict__ w2, const float* __restrict__ b2,
                           __half* __restrict__ ox, __half* __restrict__ oy)
{
    __shared__ float shs[8], shq[8];
    const int rid = blockIdx.x;
    const bool second = rid >= 4096;
    const int row = second ? rid - 4096 : rid;
    const float* xr = (second ? y : x) + (long long)row * 1024;
    const float* w  = second ? w2 : w1;
    const float* b  = second ? b2 : b1;
    __half* out     = (second ? oy : ox) + (long long)row * 1024;
    const int t = threadIdx.x;

    float4 f = *(const float4*)(xr + t * 4);
    float s = f.x + f.y + f.z + f.w;
    float q = f.x * f.x + f.y * f.y + f.z * f.z + f.w * f.w;
    #pragma unroll
    for (int o = 16; o; o >>= 1) {
        s += __shfl_xor_sync(0xFFFFFFFFu, s, o);
        q += __shfl_xor_sync(0xFFFFFFFFu, q, o);
    }
    const int wid = t >> 5, ln = t & 31;
    if (ln == 0) { shs[wid] = s; shq[wid] = q; }
    __syncthreads();
    if (wid == 0) {
        float a = (ln < 8) ? shs[ln] : 0.0f;
        float c = (ln < 8) ? shq[ln] : 0.0f;
        #pragma unroll
        for (int o = 4; o; o >>= 1) {
            a += __shfl_xor_sync(0xFFFFFFFFu, a, o);
            c += __shfl_xor_sync(0xFFFFFFFFu, c, o);
        }
        if (ln == 0) { shs[0] = a; shq[0] = c; }
    }
    __syncthreads();
    const float mu  = shs[0] * (1.0f / 1024.0f);
    const float var = shq[0] * (1.0f / 1024.0f) - mu * mu;
    const float rs  = rsqrtf(var + 1e-5f);

    float4 wv = *(const float4*)(w + t * 4);
    float4 bv = *(const float4*)(b + t * 4);
    uint2 o2;
    o2.x = f2h2((f.x - mu) * rs * wv.x + bv.x, (f.y - mu) * rs * wv.y + bv.y);
    o2.y = f2h2((f.z - mu) * rs * wv.z + bv.z, (f.w - mu) * rs * wv.w + bv.w);
    *(uint2*)(out + (long long)row * 1024 + t * 4 - (long long)row * 1024) = o2; // placate none
}

// single-input LayerNorm (for LN3)
__global__ void ln_kernel(const float* __restrict__ x,
                          const float* __restrict__ w,
                          const float* __restrict__ b,
                          __half* __restrict__ out)
{
    __shared__ float shs[8], shq[8];
    const int row = blockIdx.x;
    const float* xr = x + (long long)row * 1024;
    const int t = threadIdx.x;

    float4 f = *(const float4*)(xr + t * 4);
    float s = f.x + f.y + f.z + f.w;
    float q = f.x * f.x + f.y * f.y + f.z * f.z + f.w * f.w;
    #pragma unroll
    for (int o = 16; o; o >>= 1) {
        s += __shfl_xor_sync(0xFFFFFFFFu, s, o);
        q += __shfl_xor_sync(0xFFFFFFFFu, q, o);
    }
    const int wid = t >> 5, ln = t & 31;
    if (ln == 0) { shs[wid] = s; shq[wid] = q; }
    __syncthreads();
    if (wid == 0) {
        float a = (ln < 8) ? shs[ln] : 0.0f;
        float c = (ln < 8) ? shq[ln] : 0.0f;
        #pragma unroll
        for (int o = 4; o; o >>= 1) {
            a += __shfl_xor_sync(0xFFFFFFFFu, a, o);
            c += __shfl_xor_sync(0xFFFFFFFFu, c, o);
        }
        if (ln == 0) { shs[0] = a; shq[0] = c; }
    }
    __syncthreads();
    const float mu  = shs[0] * (1.0f / 1024.0f);
    const float var = shq[0] * (1.0f / 1024.0f) - mu * mu;
    const float rs  = rsqrtf(var + 1e-5f);

    float4 wv = *(const float4*)(w + t * 4);
    float4 bv = *(const float4*)(b + t * 4);
    uint2 o2;
    o2.x = f2h2((f.x - mu) * rs * wv.x + bv.x, (f.y - mu) * rs * wv.y + bv.y);
    o2.y = f2h2((f.z - mu) * rs * wv.z + bv.z, (f.w - mu) * rs * wv.w + bv.w);
    *(uint2*)(out + (long long)row * 1024 + t * 4) = o2;
}

// ---------------------------------------------------------------------------
// Tiled transpose + fp32->fp16: dst[n][k] = (half)src[k][n].
// ---------------------------------------------------------------------------
__global__ void transpose_f2h(const float* __restrict__ src, __half* __restrict__ dst,
                              int srcLd, int dstLd,
                              long long srcBatch, long long dstBatch)
{
    __shared__ float tile[32][33];
    const float* s = src + blockIdx.z * srcBatch;
    __half*      d = dst + blockIdx.z * dstBatch;
    const int n0 = blockIdx.x * 32, k0 = blockIdx.y * 32;
    const int tx = threadIdx.x, ty = threadIdx.y;
    #pragma unroll
    for (int j = 0; j < 32; j += 8)
        tile[ty + j][tx] = s[(long long)(k0 + ty + j) * srcLd + n0 + tx];
    __syncthreads();
    #pragma unroll
    for (int j = 0; j < 32; j += 8)
        d[(long long)(n0 + ty + j) * dstLd + k0 + tx] = __float2half_rn(tile[tx][ty + j]);
}

// Fused per-head transpose of Wq/Wk/Wv [16][1024][64] -> [1024][1024] each.
// grid (2, 32, 48): z/16 selects matrix, z%16 selects head.
__global__ void transpose_qkv(const float* __restrict__ Wq,
                              const float* __restrict__ Wk,
                              const float* __restrict__ Wv)
{
    __shared__ float tile[32][33];
    const int which = blockIdx.z >> 4;
    const int head  = blockIdx.z & 15;
    const float* s = (which == 0 ? Wq : which == 1 ? Wk : Wv) + head * 65536;
    __half*      d = (which == 0 ? g_wqp : which == 1 ? g_wkp : g_wvp) + head * 65536;
    const int n0 = blockIdx.x * 32, k0 = blockIdx.y * 32;
    const int tx = threadIdx.x, ty = threadIdx.y;
    #pragma unroll
    for (int j = 0; j < 32; j += 8)
        tile[ty + j][tx] = s[(long long)(k0 + ty + j) * 64 + n0 + tx];
    __syncthreads();
    #pragma unroll
    for (int j = 0; j < 32; j += 8)
        d[(long long)(n0 + ty + j) * 1024 + k0 + tx] = __float2half_rn(tile[tx][ty + j]);
}

// ---------------------------------------------------------------------------
// fp16 tensor-core GEMM:  C[M][N] = epi(A[M][K] @ B[N][K]^T)
// BM=128, BN=128, BK=64 (halves). 8 warps (2x4): warp tile 64x32.
// m16n8k16 f16 mma, fp32 accum. cp.async double-buffered (dynamic smem).
// smem per stage: A,B tiles [128][72] halves (stride 144B, conflict-free
// ldmatrix: 8-row phase hits banks 4r mod 32, all distinct).
// EPI: 0 = half out, alpha*acc
//      1 = float out, acc + bias[n] + res[m][n]
//      2 = half out, gelu(acc + bias[n])
// ---------------------------------------------------------------------------
#define GH_TILE_BYTES  (128 * 72 * 2)              // 18432 per matrix
#define GH_STAGE_BYTES (2 * GH_TILE_BYTES)         // 36864
#define GH_SMEM_BYTES  (2 * GH_STAGE_BYTES)        // 73728

template<int EPI>
__global__ __launch_bounds__(256, 2)
void gemm_h(int M, int N, int K,
            const __half* __restrict__ A, int lda,
            const __half* __restrict__ B, int ldb,
            void* __restrict__ Cout, int ldc,
            float alpha,
            const float* __restrict__ bias,
            const float* __restrict__ res, int ldr)
{
    extern __shared__ __half smem_g[];

    const int bm = blockIdx.y * 128;
    const int bn = blockIdx.x * 128;
    const int t    = threadIdx.x;
    const int warp = t >> 5;
    const int lane = t & 31;
    const int g  = lane >> 2;
    const int tg = lane & 3;
    const int wmBase = (warp >> 2) * 64;   // 2 warps in M
    const int wnBase = (warp & 3) * 32;    // 4 warps in N

    // ldmatrix per-lane offset (bytes), stride 72 halves
    const int sub = lane >> 3, rr = lane & 7;
    const uint32_t ldoff72 = (uint32_t)(((rr + (sub & 1) * 8) * 72 + (sub >> 1) * 8) * 2);
    const uint32_t smb = (uint32_t)__cvta_generic_to_shared(smem_g);

    float acc[4][4][4];
    #pragma unroll
    for (int i = 0; i < 4; ++i)
        #pragma unroll
        for (int j = 0; j < 4; ++j)
            #pragma unroll
            for (int q = 0; q < 4; ++q) acc[i][j][q] = 0.0f;

    auto loadStage = [&](int kt, int buf) {
        __half* Ad = smem_g + buf * (GH_STAGE_BYTES / 2);
        __half* Bd = Ad + (GH_TILE_BYTES / 2);
        const __half* Ag = A + (long long)bm * lda + kt * 64;
        const __half* Bg = B + (long long)bn * ldb + kt * 64;
        #pragma unroll
        for (int i = 0; i < 4; ++i) {
            const int id = t + i * 256;          // 1024 chunks of 16B
            const int r = id >> 3, c = id & 7;
            cp16(&Ad[r * 72 + c * 8], Ag + (long long)r * lda + c * 8);
        }
        #pragma unroll
        for (int i = 0; i < 4; ++i) {
            const int id = t + i * 256;
            const int r = id >> 3, c = id & 7;
            cp16(&Bd[r * 72 + c * 8], Bg + (long long)r * ldb + c * 8);
        }
        cp_commit();
    };

    const int nk = K >> 6;
    loadStage(0, 0);
    if (nk > 1) loadStage(1, 1);

    for (int kt = 0; kt < nk; ++kt) {
        const int buf = kt & 1;
        if (kt + 1 < nk) cp_wait1(); else cp_wait0();
        __syncthreads();

        const uint32_t aBuf = smb + (uint32_t)(buf * GH_STAGE_BYTES);
        const uint32_t bBuf = aBuf + GH_TILE_BYTES;
        #pragma unroll
        for (int ks = 0; ks < 4; ++ks) {
            const int k0 = ks * 16;
            uint32_t a[4][4], b[4][2];
            #pragma unroll
            for (int mt = 0; mt < 4; ++mt)
                ldsm4(a[mt], aBuf + (uint32_t)(((wmBase + mt * 16) * 72 + k0) * 2) + ldoff72);
            #pragma unroll
            for (int p = 0; p < 2; ++p) {
                uint32_t rb[4];
                ldsm4(rb, bBuf + (uint32_t)(((wnBase + p * 16) * 72 + k0) * 2) + ldoff72);
                b[2 * p][0]     = rb[0]; b[2 * p][1]     = rb[2];
                b[2 * p + 1][0] = rb[1]; b[2 * p + 1][1] = rb[3];
            }
            #pragma unroll
            for (int mt = 0; mt < 4; ++mt)
                #pragma unroll
                for (int nt = 0; nt < 4; ++nt)
                    mma_f16(acc[mt][nt], a[mt], b[nt]);
        }
        __syncthreads();
        if (kt + 2 < nk) loadStage(kt + 2, buf);
    }

    // ---- epilogue ----
    #pragma unroll
    for (int mt = 0; mt < 4; ++mt) {
        #pragma unroll
        for (int nt = 0; nt < 4; ++nt) {
            const int r0 = bm + wmBase + mt * 16 + g;
            const int c0 = bn + wnBase + nt * 8 + 2 * tg;
            #pragma unroll
            for (int half = 0; half < 2; ++half) {
                const int r = r0 + half * 8;
                float v0 = acc[mt][nt][half * 2 + 0];
                float v1 = acc[mt][nt][half * 2 + 1];
                if (EPI == 0) {
                    v0 *= alpha; v1 *= alpha;
                    *(uint32_t*)((__half*)Cout + (long long)r * ldc + c0) = f2h2(v0, v1);
                } else if (EPI == 1) {
                    v0 += bias[c0]     + res[(long long)r * ldr + c0];
                    v1 += bias[c0 + 1] + res[(long long)r * ldr + c0 + 1];
                    float2 o; o.x = v0; o.y = v1;
                    *(float2*)((float*)Cout + (long long)r * ldc + c0) = o;
                } else {
                    const float z0 = v0 + bias[c0];
                    const float z1 = v1 + bias[c0 + 1];
                    v0 = 0.5f * z0 * (1.0f + erff(z0 * 0.70710678118654752440f));
                    v1 = 0.5f * z1 * (1.0f + erff(z1 * 0.70710678118654752440f));
                    *(uint32_t*)((__half*)Cout + (long long)r * ldc + c0) = f2h2(v0, v1);
                }
            }
        }
    }
}

// ---------------------------------------------------------------------------
// Fused flash attention, fp16 operands, post-softmax masking.
//   O_s = (1/sum_all_t exp(s_t - m)) * sum_{t>s} exp(s_t - m) v_t
// Per CTA: one (z, 128-row) block; 8 warps x 16 rows; t-tiles of 64.
// PV + P-store skipped for tiles with tbase+63 <= bm (P provably all zero;
// l still accumulates over those tiles via S).
// ---------------------------------------------------------------------------
#define FA_SMEM_BYTES ((128*72 + 2*64*72 + 2*64*72) * 2)   // 55296

__global__ __launch_bounds__(256)
void flash_attn_kernel(const __half* __restrict__ Qg,
                       const __half* __restrict__ Kg,
                       const __half* __restrict__ Vg,
                       __half* __restrict__ Og)
{
    extern __shared__ __half sm_h[];
    __half* sP = sm_h;                           // [128][72]
    __half* sK = sm_h + 128 * 72;                // [2][64*72]
    __half* sV = sm_h + 128 * 72 + 2 * 64 * 72;  // [2][64*72]

    const int z = blockIdx.z;
    const long long zb = z >> 4, zh = z & 15;
    const long long base = zb * (2048LL * 1024) + zh * 64;
    const __half* Qp = Qg + base;
    const __half* Kp = Kg + base;
    const __half* Vp = Vg + base;

    const int bm = blockIdx.y * 128;
    const int t = threadIdx.x;
    const int w = t >> 5, lane = t & 31, g = lane >> 2, tg = lane & 3;

    const int sub = lane >> 3, rr = lane & 7;
    const uint32_t ldoff72 = (uint32_t)(((rr + (sub & 1) * 8) * 72 + (sub >> 1) * 8) * 2);
    const uint32_t sPb = (uint32_t)__cvta_generic_to_shared(sP);
    const uint32_t sKb = (uint32_t)__cvta_generic_to_shared(sK);
    const uint32_t sVb = (uint32_t)__cvta_generic_to_shared(sV);

    // ---- stage Q tile (128 x 64 halves) into sP ----
    {
        const __half* Qa = Qp + (long long)bm * 1024;
        #pragma unroll
        for (int i = 0; i < 4; ++i) {
            const int id = t + i * 256;
            const int m = id >> 3, c = id & 7;
            cp16(&sP[m * 72 + c * 8], Qa + (long long)m * 1024 + c * 8);
        }
        cp_commit();
    }

    auto loadKV = [&](int it, int buf) {
        const __half* Ka = Kp + (long long)(it * 64) * 1024;
        const __half* Va = Vp + (long long)(it * 64) * 1024;
        #pragma unroll
        for (int i = 0; i < 2; ++i) {
            const int id = t + i * 256;
            const int r = id >> 3, c = id & 7;
            cp16(&sK[buf * (64 * 72) + r * 72 + c * 8], Ka + (long long)r * 1024 + c * 8);
        }
        #pragma unroll
        for (int i = 0; i < 2; ++i) {
            const int id = t + i * 256;
            const int r = id >> 3, c = id & 7;
            cp16(&sV[buf * (64 * 72) + r * 72 + c * 8], Va + (long long)r * 1024 + c * 8);
        }
        cp_commit();
    };
    loadKV(0, 0);
    loadKV(1, 1);

    cp_wait2();
    __syncthreads();

    // ---- Q fragments (already scaled by 0.125) via ldmatrix ----
    uint32_t aq[4][4];
    #pragma unroll
    for (int kk = 0; kk < 4; ++kk)
        ldsm4(aq[kk], sPb + (uint32_t)(((w * 16) * 72 + kk * 16) * 2) + ldoff72);

    float accO[8][4];
    #pragma unroll
    for (int i = 0; i < 8; ++i)
        #pragma unroll
        for (int j = 0; j < 4; ++j) accO[i][j] = 0.0f;
    float m0 = -1e30f, m1 = -1e30f, l0 = 0.0f, l1 = 0.0f;

    const int srow0 = bm + w * 16 + g;
    const int srow1 = srow0 + 8;

    for (int it = 0; it < 32; ++it) {
        const int buf = it & 1;
        if (it + 1 < 32) cp_wait1(); else cp_wait0();
        __syncthreads();

        // ---- S = Q K^T ----
        float s[8][4];
        #pragma unroll
        for (int i = 0; i < 8; ++i) { s[i][0]=0; s[i][1]=0; s[i][2]=0; s[i][3]=0; }
        const uint32_t kBuf = sKb + (uint32_t)(buf * 64 * 72 * 2);
        #pragma unroll
        for (int kk = 0; kk < 4; ++kk) {
            const int k0 = kk * 16;
            uint32_t bfr[8][2];
            #pragma unroll
            for (int p = 0; p < 4; ++p) {
                uint32_t rb[4];
                ldsm4(rb, kBuf + (uint32_t)(((p * 16) * 72 + k0) * 2) + ldoff72);
                bfr[2 * p][0]     = rb[0]; bfr[2 * p][1]     = rb[2];
                bfr[2 * p + 1][0] = rb[1]; bfr[2 * p + 1][1] = rb[3];
            }
            #pragma unroll
            for (int nt = 0; nt < 8; ++nt)
                mma_f16(s[nt], aq[kk], bfr[nt]);
        }

        // ---- online softmax (l over ALL t; mask applies to P only) ----
        float tmax0 = s[0][0], tmax1 = s[0][2];
        #pragma unroll
        for (int nt = 0; nt < 8; ++nt) {
            tmax0 = fmaxf(tmax0, fmaxf(s[nt][0], s[nt][1]));
            tmax1 = fmaxf(tmax1, fmaxf(s[nt][2], s[nt][3]));
        }
        tmax0 = fmaxf(tmax0, __shfl_xor_sync(0xFFFFFFFFu, tmax0, 1));
        tmax0 = fmaxf(tmax0, __shfl_xor_sync(0xFFFFFFFFu, tmax0, 2));
        tmax1 = fmaxf(tmax1, __shfl_xor_sync(0xFFFFFFFFu, tmax1, 1));
        tmax1 = fmaxf(tmax1, __shfl_xor_sync(0xFFFFFFFFu, tmax1, 2));
        const float mn0 = fmaxf(m0, tmax0), mn1 = fmaxf(m1, tmax1);
        const float al0 = __expf(m0 - mn0), al1 = __expf(m1 - mn1);
        float ls0 = 0.0f, ls1 = 0.0f;
        #pragma unroll
        for (int nt = 0; nt < 8; ++nt) {
            s[nt][0] = __expf(s[nt][0] - mn0); ls0 += s[nt][0];
            s[nt][1] = __expf(s[nt][1] - mn0); ls0 += s[nt][1];
            s[nt][2] = __expf(s[nt][2] - mn1); ls1 += s[nt][2];
            s[nt][3] = __expf(s[nt][3] - mn1); ls1 += s[nt][3];
        }
        ls0 += __shfl_xor_sync(0xFFFFFFFFu, ls0, 1);
        ls0 += __shfl_xor_sync(0xFFFFFFFFu, ls0, 2);
        ls1 += __shfl_xor_sync(0xFFFFFFFFu, ls1, 1);
        ls1 += __shfl_xor_sync(0xFFFFFFFFu, ls1, 2);
        l0 = l0 * al0 + ls0;  l1 = l1 * al1 + ls1;
        m0 = mn0;  m1 = mn1;
        #pragma unroll
        for (int nt = 0; nt < 8; ++nt) {
            accO[nt][0] *= al0; accO[nt][1] *= al0;
            accO[nt][2] *= al1; accO[nt][3] *= al1;
        }

        const int tbase = it * 64;
        // Tile contributes to O only if some t > some row: max t = tbase+63,
        // min row in CTA = bm. Otherwise P is exactly zero -> skip PV.
        if (tbase + 63 > bm) {
            // ---- masked fp16 P -> sP (warp-private rows) ----
            #pragma unroll
            for (int nt = 0; nt < 8; ++nt) {
                const int tc = tbase + nt * 8 + 2 * tg;
                const float p0 = (tc     > srow0) ? s[nt][0] : 0.0f;
                const float p1 = (tc + 1 > srow0) ? s[nt][1] : 0.0f;
                const float p2 = (tc     > srow1) ? s[nt][2] : 0.0f;
                const float p3 = (tc + 1 > srow1) ? s[nt][3] : 0.0f;
                *(uint32_t*)&sP[(w * 16 + g)     * 72 + nt * 8 + 2 * tg] = f2h2(p0, p1);
                *(uint32_t*)&sP[(w * 16 + g + 8) * 72 + nt * 8 + 2 * tg] = f2h2(p2, p3);
            }
            __syncwarp();

            // ---- O += P V  (P via ldmatrix, V via ldmatrix.trans) ----
            const uint32_t vBuf = sVb + (uint32_t)(buf * 64 * 72 * 2);
            #pragma unroll
            for (int kk = 0; kk < 4; ++kk) {
                const int k0 = kk * 16;
                uint32_t a[4];
                ldsm4(a, sPb + (uint32_t)(((w * 16) * 72 + k0) * 2) + ldoff72);
                #pragma unroll
                for (int p = 0; p < 4; ++p) {
                    uint32_t rb[4];
                    ldsm4t(rb, vBuf + (uint32_t)((k0 * 72 + p * 16) * 2) + ldoff72);
                    uint32_t blo[2] = { rb[0], rb[1] };
                    uint32_t bhi[2] = { rb[2], rb[3] };
                    mma_f16(accO[2 * p],     a, blo);
                    mma_f16(accO[2 * p + 1], a, bhi);
                }
            }
        }
        __syncthreads();
        if (it + 2 < 32) loadKV(it + 2, buf);
    }

    // ---- epilogue: O /= l, write fp16 concat-head layout ----
    const float inv0 = 1.0f / l0, inv1 = 1.0f / l1;
    __half* Ob = Og + zb * (2048LL * 1024) + zh * 64;
    #pragma unroll
    for (int nt = 0; nt < 8; ++nt) {
        const int c = nt * 8 + 2 * tg;
        *(uint32_t*)(Ob + (long long)srow0 * 1024 + c) =
            f2h2(accO[nt][0] * inv0, accO[nt][1] * inv0);
        *(uint32_t*)(Ob + (long long)srow1 * 1024 + c) =
            f2h2(accO[nt][2] * inv1, accO[nt][3] * inv1);
    }
}

// ---------------------------------------------------------------------------
// Launch sequence (graph-capturable: kernel launches only)
// ---------------------------------------------------------------------------
extern "C" void kernel_launch(void* const* d_in, const int* in_sizes, int n_in,
                              void* d_out, int out_size)
{
    const float* x     = (const float*)d_in[0];
    const float* y     = (const float*)d_in[1];
    const float* Wq    = (const float*)d_in[2];
    const float* Wk    = (const float*)d_in[3];
    const float* Wv    = (const float*)d_in[4];
    const float* li1_w = (const float*)d_in[5];
    const float* li1_b = (const float*)d_in[6];
    const float* ln1_w = (const float*)d_in[7];
    const float* ln1_b = (const float*)d_in[8];
    const float* ln2_w = (const float*)d_in[9];
    const float* ln2_b = (const float*)d_in[10];
    const float* ln3_w = (const float*)d_in[11];
    const float* ln3_b = (const float*)d_in[12];
    const float* li2_w = (const float*)d_in[13];
    const float* li2_b = (const float*)d_in[14];
    const float* li3_w = (const float*)d_in[15];
    const float* li3_b = (const float*)d_in[16];
    float* out = (float*)d_out;

    __half *xn, *yn, *wqp, *wkp, *wvp, *w1t, *w2t, *w3t;
    __half *qh, *kh, *vh, *oh, *h1, *h2;
    float *xo;
    cudaGetSymbolAddress((void**)&xn,  g_xn);
    cudaGetSymbolAddress((void**)&yn,  g_yn);
    cudaGetSymbolAddress((void**)&wqp, g_wqp);
    cudaGetSymbolAddress((void**)&wkp, g_wkp);
    cudaGetSymbolAddress((void**)&wvp, g_wvp);
    cudaGetSymbolAddress((void**)&w1t, g_w1t);
    cudaGetSymbolAddress((void**)&w2t, g_w2t);
    cudaGetSymbolAddress((void**)&w3t, g_w3t);
    cudaGetSymbolAddress((void**)&qh,  g_q);
    cudaGetSymbolAddress((void**)&kh,  g_k);
    cudaGetSymbolAddress((void**)&vh,  g_v);
    cudaGetSymbolAddress((void**)&oh,  g_o);
    cudaGetSymbolAddress((void**)&h1,  g_h1);
    cudaGetSymbolAddress((void**)&h2,  g_h2);
    cudaGetSymbolAddress((void**)&xo,  g_xout);

    static int attr_set = 0;
    if (!attr_set) {
        cudaFuncSetAttribute(flash_attn_kernel,
                             cudaFuncAttributeMaxDynamicSharedMemorySize, FA_SMEM_BYTES);
        cudaFuncSetAttribute(gemm_h<0>,
                             cudaFuncAttributeMaxDynamicSharedMemorySize, GH_SMEM_BYTES);
        cudaFuncSetAttribute(gemm_h<1>,
                             cudaFuncAttributeMaxDynamicSharedMemorySize, GH_SMEM_BYTES);
        cudaFuncSetAttribute(gemm_h<2>,
                             cudaFuncAttributeMaxDynamicSharedMemorySize, GH_SMEM_BYTES);
        attr_set = 1;
    }

    const dim3 tb(32, 8);

    // 1) LayerNorms of x and y (fp16 outputs) — one launch
    ln2_kernel<<<8192, 256>>>(x, y, ln1_w, ln1_b, ln2_w, ln2_b, xn, yn);

    // 2) Transpose-pack weights to [N][K] fp16
    transpose_qkv<<<dim3(2, 32, 48), tb>>>(Wq, Wk, Wv);
    transpose_f2h<<<dim3(32, 32, 1),  tb>>>(li1_w, w1t, 1024, 1024, 0, 0);
    transpose_f2h<<<dim3(128, 32, 1), tb>>>(li2_w, w2t, 4096, 1024, 0, 0);
    transpose_f2h<<<dim3(32, 128, 1), tb>>>(li3_w, w3t, 1024, 4096, 0, 0);

    // 3) Q/K/V projections (Q pre-scaled by D^-0.5 = 0.125, exact)
    dim3 gProj(1024 / 128, 4096 / 128, 1);
    gemm_h<0><<<gProj, 256, GH_SMEM_BYTES>>>(4096, 1024, 1024, xn, 1024, wqp, 1024,
                                             qh, 1024, 0.125f, nullptr, nullptr, 0);
    gemm_h<0><<<gProj, 256, GH_SMEM_BYTES>>>(4096, 1024, 1024, yn, 1024, wkp, 1024,
                                             kh, 1024, 1.0f, nullptr, nullptr, 0);
    gemm_h<0><<<gProj, 256, GH_SMEM_BYTES>>>(4096, 1024, 1024, yn, 1024, wvp, 1024,
                                             vh, 1024, 1.0f, nullptr, nullptr, 0);

    // 4) Fused attention (scores + softmax + post-mask + PV)
    flash_attn_kernel<<<dim3(1, 16, 32), 256, FA_SMEM_BYTES>>>(qh, kh, vh, oh);

    // 5) x_out = x + O @ li1_w + li1_b  (fp32 out)
    gemm_h<1><<<gProj, 256, GH_SMEM_BYTES>>>(4096, 1024, 1024, oh, 1024, w1t, 1024,
                                             xo, 1024, 1.0f, li1_b, x, 1024);

    // 6) h1 = LN(x_out) (fp16)
    ln_kernel<<<4096, 256>>>(xo, ln3_w, ln3_b, h1);

    // 7) h2 = gelu(h1 @ li2_w + li2_b)  (fp16)
    dim3 gUp(4096 / 128, 4096 / 128, 1);
    gemm_h<2><<<gUp, 256, GH_SMEM_BYTES>>>(4096, 4096, 1024, h1, 1024, w2t, 1024,
                                           h2, 4096, 1.0f, li2_b, nullptr, 0);

    // 8) out = x_out + h2 @ li3_w + li3_b  (fp32 out)
    dim3 gDn(1024 / 128, 4096 / 128, 1);
    gemm_h<1><<<gDn, 256, GH_SMEM_BYTES>>>(4096, 1024, 4096, h2, 4096, w3t, 4096,
                                           out, 1024, 1.0f, li3_b, xo, 1024);
}